// round 3
// baseline (speedup 1.0000x reference)
#include <cuda_runtime.h>
#include <cuda_bf16.h>

// ---------------------------------------------------------------------------
// MultiHeadAttention: B=16, L=512, D=512, H=8, DK=DV=64, TEMP=8
// out = ( output[16,512], attn[128,512,512] ) concatenated in d_out (fp32)
// ---------------------------------------------------------------------------

typedef unsigned long long u64t;

// ------------------------- scratch (static device mem) ---------------------
__device__ __align__(16) float g_qh[8 * 16 * 512 * 64];   // [h][b][l][d]
__device__ __align__(16) float g_kh[8 * 16 * 512 * 64];
__device__ __align__(16) float g_vh[8 * 16 * 512 * 64];
__device__ __align__(16) float g_act[16 * 512 * 512];     // [b][l][h][dv] = out_flat
__device__ __align__(16) float g_part[128 * 512 * 16];    // [ksplit][o][b]

// ------------------------- f32x2 helpers -----------------------------------
__device__ __forceinline__ u64t dup2(float x) {
    u64t r; asm("mov.b64 %0,{%1,%1};" : "=l"(r) : "f"(x)); return r;
}
__device__ __forceinline__ u64t pack2f(float x, float y) {
    u64t r; asm("mov.b64 %0,{%1,%2};" : "=l"(r) : "f"(x), "f"(y)); return r;
}
__device__ __forceinline__ void fma2(u64t& d, u64t a, u64t b) {
    asm("fma.rn.f32x2 %0,%1,%2,%3;" : "=l"(d) : "l"(a), "l"(b), "l"(d));
}
__device__ __forceinline__ u64t add2(u64t a, u64t b) {
    u64t r; asm("add.rn.f32x2 %0,%1,%2;" : "=l"(r) : "l"(a), "l"(b)); return r;
}
__device__ __forceinline__ u64t mul2(u64t a, u64t b) {
    u64t r; asm("mul.rn.f32x2 %0,%1,%2;" : "=l"(r) : "l"(a), "l"(b)); return r;
}
__device__ __forceinline__ float2 unp2(u64t v) {
    float2 f; asm("mov.b64 {%0,%1},%2;" : "=f"(f.x), "=f"(f.y) : "l"(v)); return f;
}

// ===========================================================================
// Projection kernel: C[m,n] = sum_k X[m,k]*W[n,k] + bias[n]
// X: [8192,512], W: [512,512].  Output scattered to head-major scratch
// [h][b][l][d].  grid = (8 ntiles, 128 mtiles, 3 projections), block = 128.
// Micro-tile 4x8 per thread (f32x2 over n-pairs). Both smem tiles k-major.
// ===========================================================================
#define PKC 32
#define TP 68   // tile pad

__global__ void __launch_bounds__(128) proj_kernel(
    const float* __restrict__ q, const float* __restrict__ k,
    const float* __restrict__ v,
    const float* __restrict__ Wq, const float* __restrict__ bq,
    const float* __restrict__ Wk, const float* __restrict__ bk,
    const float* __restrict__ Wv, const float* __restrict__ bv)
{
    __shared__ float Xs[PKC][TP];
    __shared__ float Ws[PKC][TP];

    const int z = blockIdx.z;
    const float* X    = (z == 0) ? q  : (z == 1) ? k  : v;
    const float* W    = (z == 0) ? Wq : (z == 1) ? Wk : Wv;
    const float* bias = (z == 0) ? bq : (z == 1) ? bk : bv;
    float* dst        = (z == 0) ? g_qh : (z == 1) ? g_kh : g_vh;

    const int n0 = blockIdx.x * 64;           // head = blockIdx.x
    const int m0 = blockIdx.y * 64;
    const int tid = threadIdx.x;
    const int tr = tid & 15;                  // 16 row groups (4 rows each)
    const int tc = tid >> 4;                  // 8 col groups (8 cols = 4 pairs)

    u64t acc[4][4];
#pragma unroll
    for (int r = 0; r < 4; r++)
#pragma unroll
        for (int c = 0; c < 4; c++) acc[r][c] = 0ull;

    for (int kc = 0; kc < 512; kc += PKC) {
        __syncthreads();
        // load + transpose tiles: 64 rows x PKC(32) k-chunk = 512 float4
        for (int f = tid; f < 512; f += 128) {
            int row = f >> 3, c = f & 7;
            float4 x4 = *(const float4*)&X[(size_t)(m0 + row) * 512 + kc + c * 4];
            Xs[c * 4 + 0][row] = x4.x; Xs[c * 4 + 1][row] = x4.y;
            Xs[c * 4 + 2][row] = x4.z; Xs[c * 4 + 3][row] = x4.w;
            float4 w4 = *(const float4*)&W[(size_t)(n0 + row) * 512 + kc + c * 4];
            Ws[c * 4 + 0][row] = w4.x; Ws[c * 4 + 1][row] = w4.y;
            Ws[c * 4 + 2][row] = w4.z; Ws[c * 4 + 3][row] = w4.w;
        }
        __syncthreads();

#pragma unroll 4
        for (int kk = 0; kk < PKC; kk++) {
            float4 a4 = *(const float4*)&Xs[kk][tr * 4];
            u64t a2[4] = { dup2(a4.x), dup2(a4.y), dup2(a4.z), dup2(a4.w) };
            u64t b2[4];
#pragma unroll
            for (int c2 = 0; c2 < 4; c2++)
                b2[c2] = *(const u64t*)&Ws[kk][tc * 8 + 2 * c2];
#pragma unroll
            for (int r = 0; r < 4; r++)
#pragma unroll
                for (int c2 = 0; c2 < 4; c2++)
                    fma2(acc[r][c2], a2[r], b2[c2]);
        }
    }

    // epilogue: scatter to [h][b][l][d] scratch, add bias
    const int hh = blockIdx.x;
    const int bb = m0 >> 9;
    const int l0 = (m0 & 511) + tr * 4;
#pragma unroll
    for (int r = 0; r < 4; r++) {
        int l = l0 + r;
        size_t rowbase = ((size_t)(hh * 16 + bb) * 512 + l) * 64;
#pragma unroll
        for (int c2 = 0; c2 < 4; c2++) {
            int d0 = tc * 8 + 2 * c2;
            u64t bias2 = *(const u64t*)&bias[n0 + d0];
            *(u64t*)&dst[rowbase + d0] = add2(acc[r][c2], bias2);
        }
    }
}

// ===========================================================================
// Attention kernel: CTA per (hb, qtile of 64). 256 threads.
// Phase 1: S[n][q] = QK^T/8 into smem strip (512 x 64, pad 66)
// Phase 2: row softmax (warp per 8 q rows), write attn to d_out, inv[] kept
// Phase 3: O = P V with n split across thread halves + smem combine -> g_act
// ===========================================================================
#define SB_PAD 66
#define SB_SZ  (512 * SB_PAD)        // 33792 floats
#define QOFF   SB_SZ                 // Qs: [d][q] pad 68 (4352 floats); reused as combine buf
#define KOFF   (QOFF + 64 * 68)      // KV tile: QK: [d][n128] pad 136; PV: [n128][dv] pad 68 (8704)
#define IOFF   (KOFF + 8704)         // inv[64]
#define ATTN_SMEM_FLOATS (IOFF + 64)
#define ATTN_SMEM_BYTES  (ATTN_SMEM_FLOATS * 4)

__global__ void __launch_bounds__(256) attn_kernel(float* __restrict__ attn_out)
{
    extern __shared__ float sm[];
    const int tid = threadIdx.x;
    const int hb = blockIdx.y;               // h*16 + b
    const int q0 = blockIdx.x * 64;

    // ---- load Q tile transposed: Qs[d][q] ----
    for (int f = tid; f < 1024; f += 256) {
        int row = f >> 4, c = f & 15;
        float4 v4 = *(const float4*)&g_qh[((size_t)hb * 512 + q0 + row) * 64 + c * 4];
        sm[QOFF + (c * 4 + 0) * 68 + row] = v4.x;
        sm[QOFF + (c * 4 + 1) * 68 + row] = v4.y;
        sm[QOFF + (c * 4 + 2) * 68 + row] = v4.z;
        sm[QOFF + (c * 4 + 3) * 68 + row] = v4.w;
    }

    // ---- Phase 1: QK^T ----
    {
        const int trn = tid & 31;            // 32 n-groups (4 rows each -> 128)
        const int tcq = tid >> 5;            // warp id: 8 q-groups (8 q = 4 pairs)
        const u64t scale = dup2(0.125f);

        for (int nt = 0; nt < 4; nt++) {
            __syncthreads();
            // K tile transposed: Ks[d][n] pad 136
            for (int f = tid; f < 2048; f += 256) {
                int row = f >> 4, c = f & 15;
                float4 v4 = *(const float4*)&g_kh[((size_t)hb * 512 + nt * 128 + row) * 64 + c * 4];
                sm[KOFF + (c * 4 + 0) * 136 + row] = v4.x;
                sm[KOFF + (c * 4 + 1) * 136 + row] = v4.y;
                sm[KOFF + (c * 4 + 2) * 136 + row] = v4.z;
                sm[KOFF + (c * 4 + 3) * 136 + row] = v4.w;
            }
            __syncthreads();

            u64t acc[4][4];
#pragma unroll
            for (int r = 0; r < 4; r++)
#pragma unroll
                for (int c = 0; c < 4; c++) acc[r][c] = 0ull;

#pragma unroll 4
            for (int kk = 0; kk < 64; kk++) {
                float4 a4 = *(const float4*)&sm[KOFF + kk * 136 + trn * 4];
                u64t a2[4] = { dup2(a4.x), dup2(a4.y), dup2(a4.z), dup2(a4.w) };
                u64t b2[4];
#pragma unroll
                for (int c2 = 0; c2 < 4; c2++)
                    b2[c2] = *(const u64t*)&sm[QOFF + kk * 68 + tcq * 8 + 2 * c2];
#pragma unroll
                for (int r = 0; r < 4; r++)
#pragma unroll
                    for (int c2 = 0; c2 < 4; c2++)
                        fma2(acc[r][c2], a2[r], b2[c2]);
            }
            // store: S[n][q-pair], scaled by 1/TEMP
#pragma unroll
            for (int r = 0; r < 4; r++) {
                int n = nt * 128 + trn * 4 + r;
#pragma unroll
                for (int c2 = 0; c2 < 4; c2++)
                    *(u64t*)&sm[n * SB_PAD + tcq * 8 + 2 * c2] = mul2(acc[r][c2], scale);
            }
        }
    }
    __syncthreads();

    // ---- Phase 2: softmax rows + write attn ----
    {
        const int warp = tid >> 5, lane = tid & 31;
        for (int qi = 0; qi < 8; qi++) {
            int ql = warp * 8 + qi;
            float m = -3.4e38f;
#pragma unroll
            for (int s = 0; s < 16; s++)
                m = fmaxf(m, sm[(lane + 32 * s) * SB_PAD + ql]);
#pragma unroll
            for (int off = 16; off >= 1; off >>= 1)
                m = fmaxf(m, __shfl_xor_sync(0xffffffffu, m, off));
            float sum = 0.f;
#pragma unroll
            for (int s = 0; s < 16; s++) {
                int n = lane + 32 * s;
                float e = __expf(sm[n * SB_PAD + ql] - m);
                sm[n * SB_PAD + ql] = e;
                sum += e;
            }
#pragma unroll
            for (int off = 16; off >= 1; off >>= 1)
                sum += __shfl_xor_sync(0xffffffffu, sum, off);
            float iv = 1.0f / sum;
            if (lane == 0) sm[IOFF + ql] = iv;
            float* drow = attn_out + ((size_t)hb * 512 + q0 + ql) * 512;
#pragma unroll
            for (int s = 0; s < 16; s++) {
                int n = lane + 32 * s;
                drow[n] = sm[n * SB_PAD + ql] * iv;
            }
        }
    }
    __syncthreads();

    // ---- Phase 3: O = P V (unnormalized P, scale by inv at store) ----
    {
        const int trv = tid & 15;            // 16 dv-groups (4 each)
        const int tcq = (tid >> 4) & 7;      // 8 q-groups (8 q = 4 pairs)
        const int nh  = tid >> 7;            // n-half (0/1)

        u64t acc[4][4];                      // [dv r][q pair c2]
#pragma unroll
        for (int r = 0; r < 4; r++)
#pragma unroll
            for (int c = 0; c < 4; c++) acc[r][c] = 0ull;

        for (int nt = 0; nt < 4; nt++) {
            __syncthreads();
            // V tile direct: Vs[n][dv] pad 68
            for (int f = tid; f < 2048; f += 256) {
                int row = f >> 4, c = f & 15;
                float4 v4 = *(const float4*)&g_vh[((size_t)hb * 512 + nt * 128 + row) * 64 + c * 4];
                *(float4*)&sm[KOFF + row * 68 + c * 4] = v4;
            }
            __syncthreads();

#pragma unroll 4
            for (int kk2 = 0; kk2 < 64; kk2++) {
                int kk = nh * 64 + kk2;
                int n = nt * 128 + kk;
                float4 a4 = *(const float4*)&sm[KOFF + kk * 68 + trv * 4];
                u64t a2[4] = { dup2(a4.x), dup2(a4.y), dup2(a4.z), dup2(a4.w) };
                u64t b2[4];
#pragma unroll
                for (int c2 = 0; c2 < 4; c2++)
                    b2[c2] = *(const u64t*)&sm[n * SB_PAD + tcq * 8 + 2 * c2];
#pragma unroll
                for (int r = 0; r < 4; r++)
#pragma unroll
                    for (int c2 = 0; c2 < 4; c2++)
                        fma2(acc[r][c2], a2[r], b2[c2]);
            }
        }
        __syncthreads();
        // combine halves via smem (reuse Qs region)
        if (nh == 1) {
            int t = tid & 127;
#pragma unroll
            for (int r = 0; r < 4; r++)
#pragma unroll
                for (int c2 = 0; c2 < 4; c2++)
                    *(u64t*)&sm[QOFF + t * 32 + (r * 4 + c2) * 2] = acc[r][c2];
        }
        __syncthreads();
        if (nh == 0) {
            const int bb = hb & 15, hh = hb >> 4;
#pragma unroll
            for (int r = 0; r < 4; r++) {
                int dv = trv * 4 + r;
#pragma unroll
                for (int c2 = 0; c2 < 4; c2++) {
                    u64t other = *(const u64t*)&sm[QOFF + tid * 32 + (r * 4 + c2) * 2];
                    u64t tot = add2(acc[r][c2], other);
                    int qlo = tcq * 8 + 2 * c2;
                    u64t iv2 = pack2f(sm[IOFF + qlo], sm[IOFF + qlo + 1]);
                    float2 res = unp2(mul2(tot, iv2));
                    size_t base0 = (((size_t)bb * 512 + q0 + qlo) * 8 + hh) * 64 + dv;
                    size_t base1 = (((size_t)bb * 512 + q0 + qlo + 1) * 8 + hh) * 64 + dv;
                    g_act[base0] = res.x;
                    g_act[base1] = res.y;
                }
            }
        }
    }
}

// ===========================================================================
// FC kernel: out[b][o] = sum_i act[b][i] * Wf[o][i]   (I = 262144)
// grid (128 ksplits, 16 oblocks), block 256. Warp handles 4 outputs.
// act chunk staged in smem as batch-pair float2 -> 8 FFMA2 per Wf scalar.
// Deterministic split-K partials -> reduce kernel.
// ===========================================================================
#define FC_KC 2048
#define FC_SMEM_BYTES (8 * FC_KC * 8)    // 8 float2-rows x 2048 = 131072 B

__global__ void __launch_bounds__(256) fc_kernel(const float* __restrict__ Wf)
{
    extern __shared__ float2 sm2[];      // [b2][FC_KC]
    const int tid = threadIdx.x;
    const int k0 = blockIdx.x * FC_KC;
    const int o0 = blockIdx.y * 32;

    // stage act chunk: 16 rows x 2048 floats = 8192 float4
    const float4* act4 = (const float4*)g_act;
    float* smf = (float*)sm2;
    for (int f = tid; f < 8192; f += 256) {
        int b = f >> 9, c = f & 511;
        float4 v = act4[(size_t)b * 65536 + (k0 >> 2) + c];
        int b2 = b >> 1, lo = b & 1;
        float* p = &smf[(b2 * FC_KC + c * 4) * 2 + lo];
        p[0] = v.x; p[2] = v.y; p[4] = v.z; p[6] = v.w;
    }
    __syncthreads();

    const int warp = tid >> 5, lane = tid & 31;
    const int ob = o0 + warp * 4;

    u64t acc[4][8];
#pragma unroll
    for (int j = 0; j < 4; j++)
#pragma unroll
        for (int b2 = 0; b2 < 8; b2++) acc[j][b2] = 0ull;

    const float* w0 = Wf + (size_t)(ob + 0) * 262144 + k0;
    const float* w1 = Wf + (size_t)(ob + 1) * 262144 + k0;
    const float* w2 = Wf + (size_t)(ob + 2) * 262144 + k0;
    const float* w3 = Wf + (size_t)(ob + 3) * 262144 + k0;

#pragma unroll 2
    for (int i = lane; i < FC_KC; i += 32) {
        u64t wd[4] = { dup2(w0[i]), dup2(w1[i]), dup2(w2[i]), dup2(w3[i]) };
        u64t a[8];
#pragma unroll
        for (int b2 = 0; b2 < 8; b2++)
            a[b2] = *(const u64t*)&sm2[b2 * FC_KC + i];
#pragma unroll
        for (int j = 0; j < 4; j++)
#pragma unroll
            for (int b2 = 0; b2 < 8; b2++)
                fma2(acc[j][b2], wd[j], a[b2]);
    }

    // warp reduction (packed adds), lane 0 writes partials
#pragma unroll
    for (int j = 0; j < 4; j++)
#pragma unroll
        for (int b2 = 0; b2 < 8; b2++) {
#pragma unroll
            for (int off = 16; off >= 1; off >>= 1) {
                u64t o = __shfl_down_sync(0xffffffffu, acc[j][b2], off);
                acc[j][b2] = add2(acc[j][b2], o);
            }
        }
    if (lane == 0) {
#pragma unroll
        for (int j = 0; j < 4; j++) {
            size_t base = ((size_t)blockIdx.x * 512 + ob + j) * 16;
#pragma unroll
            for (int b2 = 0; b2 < 8; b2++) {
                float2 f = unp2(acc[j][b2]);
                g_part[base + 2 * b2]     = f.x;
                g_part[base + 2 * b2 + 1] = f.y;
            }
        }
    }
}

__global__ void reduce_fc(const float* __restrict__ bf, float* __restrict__ out)
{
    int t = blockIdx.x * 256 + threadIdx.x;     // 8192 = 512 o x 16 b
    int o = t >> 4, b = t & 15;
    float s = 0.f;
#pragma unroll 8
    for (int ks = 0; ks < 128; ks++)
        s += g_part[((size_t)ks * 512 + o) * 16 + b];
    out[b * 512 + o] = s + bf[o];
}

// ===========================================================================
extern "C" void kernel_launch(void* const* d_in, const int* in_sizes, int n_in,
                              void* d_out, int out_size)
{
    const float* q  = (const float*)d_in[0];
    const float* k  = (const float*)d_in[1];
    const float* v  = (const float*)d_in[2];
    const float* Wq = (const float*)d_in[3];
    const float* bq = (const float*)d_in[4];
    const float* Wk = (const float*)d_in[5];
    const float* bk = (const float*)d_in[6];
    const float* Wv = (const float*)d_in[7];
    const float* bv = (const float*)d_in[8];
    const float* Wf = (const float*)d_in[9];
    const float* bf = (const float*)d_in[10];
    float* out = (float*)d_out;

    cudaFuncSetAttribute(attn_kernel, cudaFuncAttributeMaxDynamicSharedMemorySize,
                         ATTN_SMEM_BYTES);
    cudaFuncSetAttribute(fc_kernel, cudaFuncAttributeMaxDynamicSharedMemorySize,
                         FC_SMEM_BYTES);

    proj_kernel<<<dim3(8, 128, 3), 128>>>(q, k, v, Wq, bq, Wk, bk, Wv, bv);
    attn_kernel<<<dim3(8, 128), 256, ATTN_SMEM_BYTES>>>(out + 8192);
    fc_kernel<<<dim3(128, 16), 256, FC_SMEM_BYTES>>>(Wf);
    reduce_fc<<<32, 256>>>(bf, out);
}

// round 5
// speedup vs baseline: 1.7000x; 1.7000x over previous
#include <cuda_runtime.h>
#include <cuda_bf16.h>
#include <cstdint>

// ---------------------------------------------------------------------------
// MultiHeadAttention: B=16, L=512, D=512, H=8, DK=DV=64, TEMP=8
// out = ( output[16,512], attn[128,512,512] ) concatenated in d_out (fp32)
// R4: mma.sync bf16-split projections (sm_103-safe) + 512-thread attention
// ---------------------------------------------------------------------------

typedef unsigned long long u64t;

// ------------------------- scratch (static device mem) ---------------------
__device__ __align__(16) float g_qh[8 * 16 * 512 * 64];   // [h][b][l][d]
__device__ __align__(16) float g_kh[8 * 16 * 512 * 64];
__device__ __align__(16) float g_vh[8 * 16 * 512 * 64];
__device__ __align__(16) float g_act[16 * 512 * 512];     // [b][l][h][dv]
__device__ __align__(16) float g_part[256 * 512 * 16];    // [ksplit][o][b]
__device__ __align__(16) __nv_bfloat16 g_xhi[3 * 8192 * 512];
__device__ __align__(16) __nv_bfloat16 g_xlo[3 * 8192 * 512];
__device__ __align__(16) __nv_bfloat16 g_whi[3 * 512 * 512];
__device__ __align__(16) __nv_bfloat16 g_wlo[3 * 512 * 512];

// ------------------------- f32x2 helpers -----------------------------------
__device__ __forceinline__ u64t dup2(float x) {
    u64t r; asm("mov.b64 %0,{%1,%1};" : "=l"(r) : "f"(x)); return r;
}
__device__ __forceinline__ void fma2(u64t& d, u64t a, u64t b) {
    asm("fma.rn.f32x2 %0,%1,%2,%3;" : "=l"(d) : "l"(a), "l"(b), "l"(d));
}
__device__ __forceinline__ u64t add2(u64t a, u64t b) {
    u64t r; asm("add.rn.f32x2 %0,%1,%2;" : "=l"(r) : "l"(a), "l"(b)); return r;
}
__device__ __forceinline__ u64t mul2(u64t a, u64t b) {
    u64t r; asm("mul.rn.f32x2 %0,%1,%2;" : "=l"(r) : "l"(a), "l"(b)); return r;
}
__device__ __forceinline__ float2 unp2(u64t v) {
    float2 f; asm("mov.b64 {%0,%1},%2;" : "=f"(f.x), "=f"(f.y) : "l"(v)); return f;
}

// ------------------------- mma/ldmatrix/cp.async helpers --------------------
__device__ __forceinline__ uint32_t smem_u32(const void* p) {
    uint32_t a;
    asm("{ .reg .u64 t; cvta.to.shared.u64 t, %1; cvt.u32.u64 %0, t; }"
        : "=r"(a) : "l"(p));
    return a;
}
__device__ __forceinline__ void ldm4(uint32_t* r, uint32_t addr) {
    asm volatile("ldmatrix.sync.aligned.m8n8.x4.shared.b16 {%0,%1,%2,%3}, [%4];"
                 : "=r"(r[0]), "=r"(r[1]), "=r"(r[2]), "=r"(r[3]) : "r"(addr));
}
__device__ __forceinline__ void mma16816(float* c, const uint32_t* a,
                                         const uint32_t* b) {
    asm volatile(
        "mma.sync.aligned.m16n8k16.row.col.f32.bf16.bf16.f32 "
        "{%0,%1,%2,%3}, {%4,%5,%6,%7}, {%8,%9}, {%0,%1,%2,%3};"
        : "+f"(c[0]), "+f"(c[1]), "+f"(c[2]), "+f"(c[3])
        : "r"(a[0]), "r"(a[1]), "r"(a[2]), "r"(a[3]), "r"(b[0]), "r"(b[1]));
}
__device__ __forceinline__ void cpa16(uint32_t sa, const void* ga) {
    asm volatile("cp.async.cg.shared.global [%0], [%1], 16;"
                 :: "r"(sa), "l"(ga) : "memory");
}
__device__ __forceinline__ void cpa_commit() {
    asm volatile("cp.async.commit_group;" ::: "memory");
}
template <int N>
__device__ __forceinline__ void cpa_wait() {
    asm volatile("cp.async.wait_group %0;" :: "n"(N) : "memory");
}

// ===========================================================================
// cvt_kernel: fp32 -> (bf16 hi, bf16 lo) split for X (q,k,v) and W (Wq,Wk,Wv)
// ===========================================================================
__global__ void __launch_bounds__(256) cvt_kernel(
    const float* __restrict__ q, const float* __restrict__ k,
    const float* __restrict__ v,
    const float* __restrict__ Wq, const float* __restrict__ Wk,
    const float* __restrict__ Wv)
{
    const int t = blockIdx.x * 256 + threadIdx.x;       // one float4 per thread
    const int XN4 = 3 * 1048576;
    const int WN4 = 3 * 65536;
    if (t >= XN4 + WN4) return;

    const float* src;
    __nv_bfloat16 *dh, *dl;
    size_t off4;
    if (t < XN4) {
        int z = t >> 20, i = t & 1048575;
        src = (z == 0) ? q : (z == 1) ? k : v;
        dh = g_xhi + (size_t)z * 4194304; dl = g_xlo + (size_t)z * 4194304;
        off4 = i;
    } else {
        int t2 = t - XN4;
        int z = t2 >> 16, i = t2 & 65535;
        src = (z == 0) ? Wq : (z == 1) ? Wk : Wv;
        dh = g_whi + (size_t)z * 262144; dl = g_wlo + (size_t)z * 262144;
        off4 = i;
    }
    float4 x = *(const float4*)(src + off4 * 4);
    float a[4] = { x.x, x.y, x.z, x.w };
    __nv_bfloat16 h[4], l[4];
#pragma unroll
    for (int j = 0; j < 4; j++) {
        h[j] = __float2bfloat16(a[j]);
        l[j] = __float2bfloat16(a[j] - __bfloat162float(h[j]));
    }
    __nv_bfloat162* ph = (__nv_bfloat162*)(dh + off4 * 4);
    __nv_bfloat162* pl = (__nv_bfloat162*)(dl + off4 * 4);
    ph[0] = __halves2bfloat162(h[0], h[1]); ph[1] = __halves2bfloat162(h[2], h[3]);
    pl[0] = __halves2bfloat162(l[0], l[1]); pl[1] = __halves2bfloat162(l[2], l[3]);
}

// ===========================================================================
// proj_mma: mma.sync bf16 split-2 GEMM. CTA tile M=128, N=128, K=512,
// K-chunk 64 double-buffered via cp.async. 8 warps, warp tile 32x64.
// C[m,n] = sum_k X[m,k]*W[n,k] (+bias), scattered to [h][b][l][d] scratch.
// grid (4 ntiles, 64 mtiles, 3 z), block 256.
// ===========================================================================
#define RS     144                 // smem row stride bytes (72 halves, padded)
#define MHALF  18432               // one 128x64 bf16 matrix (padded)
#define CH_BUF 73728               // A_hi + A_lo + B_hi + B_lo
#define PJ_SMEM (2 * CH_BUF)

__global__ void __launch_bounds__(256) proj_mma(
    const float* __restrict__ bq, const float* __restrict__ bk,
    const float* __restrict__ bv)
{
    extern __shared__ char smem[];
    const uint32_t sb = smem_u32(smem);
    const int tid = threadIdx.x;
    const int wid = tid >> 5, lane = tid & 31;
    const int warp_m = wid & 3, warp_n = wid >> 2;     // 4x2 warp grid

    const int z = blockIdx.z;
    const int m0 = blockIdx.y * 128;
    const int n0 = blockIdx.x * 128;
    const float* bias = (z == 0) ? bq : (z == 1) ? bk : bv;
    float* dst = (z == 0) ? g_qh : (z == 1) ? g_kh : g_vh;

    const __nv_bfloat16* gm[4] = {
        g_xhi + ((size_t)z * 8192 + m0) * 512,
        g_xlo + ((size_t)z * 8192 + m0) * 512,
        g_whi + ((size_t)z * 512 + n0) * 512,
        g_wlo + ((size_t)z * 512 + n0) * 512 };

    // ldmatrix per-lane address components
    const uint32_t a_row  = lane & 15;
    const uint32_t a_koff = (lane >> 4) * 8;           // halves
    const uint32_t b_nrow = ((lane >> 4) * 8) + (lane & 7);
    const uint32_t b_koff = ((lane >> 3) & 1) * 8;     // halves

    float acc[2][8][4];
#pragma unroll
    for (int mt = 0; mt < 2; mt++)
#pragma unroll
        for (int nt = 0; nt < 8; nt++)
#pragma unroll
            for (int j = 0; j < 4; j++) acc[mt][nt][j] = 0.f;

    // ---- async load of chunk c into buffer (c&1) ----
    auto load_chunk = [&](int c) {
        const int kc = c * 64;
        const uint32_t base = sb + (uint32_t)(c & 1) * CH_BUF;
#pragma unroll
        for (int mat = 0; mat < 4; mat++) {
            const __nv_bfloat16* g = gm[mat];
#pragma unroll
            for (int i = 0; i < 4; i++) {
                int idx = tid + i * 256;               // 0..1023
                int row = idx >> 3, seg = idx & 7;
                cpa16(base + mat * MHALF + row * RS + seg * 16,
                      g + (size_t)row * 512 + kc + seg * 8);
            }
        }
        cpa_commit();
    };

    load_chunk(0);
    load_chunk(1);

    for (int c = 0; c < 8; c++) {
        if (c < 7) cpa_wait<1>(); else cpa_wait<0>();
        __syncthreads();

        const uint32_t bufb = sb + (uint32_t)(c & 1) * CH_BUF;
        const uint32_t aBase = bufb + (warp_m * 32 + a_row) * RS + a_koff * 2;
        const uint32_t bBase = bufb + 2 * MHALF +
                               (warp_n * 64 + b_nrow) * RS + b_koff * 2;
#pragma unroll
        for (int ks = 0; ks < 4; ks++) {
            uint32_t aH[2][4], aL[2][4], bH[8][2], bL[8][2];
#pragma unroll
            for (int mt = 0; mt < 2; mt++) {
                uint32_t ad = aBase + mt * 16 * RS + ks * 32;
                ldm4(aH[mt], ad);
                ldm4(aL[mt], ad + MHALF);
            }
#pragma unroll
            for (int nb = 0; nb < 4; nb++) {
                uint32_t bd = bBase + nb * 16 * RS + ks * 32;
                uint32_t r[4];
                ldm4(r, bd);
                bH[2 * nb][0] = r[0]; bH[2 * nb][1] = r[1];
                bH[2 * nb + 1][0] = r[2]; bH[2 * nb + 1][1] = r[3];
                ldm4(r, bd + MHALF);
                bL[2 * nb][0] = r[0]; bL[2 * nb][1] = r[1];
                bL[2 * nb + 1][0] = r[2]; bL[2 * nb + 1][1] = r[3];
            }
#pragma unroll
            for (int mt = 0; mt < 2; mt++)
#pragma unroll
                for (int nt = 0; nt < 8; nt++) {
                    mma16816(acc[mt][nt], aH[mt], bH[nt]);
                    mma16816(acc[mt][nt], aH[mt], bL[nt]);
                    mma16816(acc[mt][nt], aL[mt], bH[nt]);
                }
        }
        __syncthreads();
        if (c + 2 < 8) load_chunk(c + 2);
    }

    // ---- epilogue: regs -> smem stage (pad 132) -> coalesced global ----
    float* stage = (float*)smem;
#pragma unroll
    for (int mt = 0; mt < 2; mt++)
#pragma unroll
        for (int nt = 0; nt < 8; nt++) {
            int row = warp_m * 32 + mt * 16 + (lane >> 2);
            int col = warp_n * 64 + nt * 8 + (lane & 3) * 2;
            *(float2*)&stage[row * 132 + col] =
                make_float2(acc[mt][nt][0], acc[mt][nt][1]);
            *(float2*)&stage[(row + 8) * 132 + col] =
                make_float2(acc[mt][nt][2], acc[mt][nt][3]);
        }
    __syncthreads();

    for (int f = tid; f < 4096; f += 256) {
        int row = f >> 5, c4 = f & 31;
        int nn = c4 * 4;
        int rg = m0 + row, bb = rg >> 9, ll = rg & 511;
        int hh = (n0 + nn) >> 6, d = nn & 63;
        float4 r;
        r.x = stage[row * 132 + nn + 0] + __ldg(&bias[n0 + nn + 0]);
        r.y = stage[row * 132 + nn + 1] + __ldg(&bias[n0 + nn + 1]);
        r.z = stage[row * 132 + nn + 2] + __ldg(&bias[n0 + nn + 2]);
        r.w = stage[row * 132 + nn + 3] + __ldg(&bias[n0 + nn + 3]);
        *(float4*)&dst[(((size_t)hh * 16 + bb) * 512 + ll) * 64 + d] = r;
    }
}

// ===========================================================================
// Attention kernel: CTA per (hb, qtile 64). 512 threads (16 warps).
// Phase 1: S[n][q] = QK^T/8.  Phase 2: softmax + attn writeback.
// Phase 3: O = P V (dv-pairs, 4-way n-split, coalesced float4 output).
// ===========================================================================
#define SB_PAD 66
#define SB_SZ  (512 * SB_PAD)
#define QOFF   SB_SZ
#define KOFF   (QOFF + 64 * 68)
#define IOFF   (KOFF + 8704)
#define ATTN_SMEM_BYTES  ((IOFF + 64) * 4)

__global__ void __launch_bounds__(512) attn_kernel(float* __restrict__ attn_out)
{
    extern __shared__ float sm[];
    const int tid = threadIdx.x;
    const int hb = blockIdx.y;
    const int q0 = blockIdx.x * 64;

    // Q tile transposed: Qs[d][q] pad 68
    for (int f = tid; f < 1024; f += 512) {
        int row = f >> 4, c = f & 15;
        float4 v4 = *(const float4*)&g_qh[((size_t)hb * 512 + q0 + row) * 64 + c * 4];
        sm[QOFF + (c * 4 + 0) * 68 + row] = v4.x;
        sm[QOFF + (c * 4 + 1) * 68 + row] = v4.y;
        sm[QOFF + (c * 4 + 2) * 68 + row] = v4.z;
        sm[QOFF + (c * 4 + 3) * 68 + row] = v4.w;
    }

    // ---- Phase 1: QK^T ----
    {
        const int trn = tid & 31;
        const int tcq = tid >> 5;            // warp id: 16 q-groups of 4
        const u64t scale = dup2(0.125f);

        for (int nt = 0; nt < 4; nt++) {
            __syncthreads();
            for (int f = tid; f < 2048; f += 512) {
                int row = f >> 4, c = f & 15;
                float4 v4 = *(const float4*)&g_kh[((size_t)hb * 512 + nt * 128 + row) * 64 + c * 4];
                sm[KOFF + (c * 4 + 0) * 136 + row] = v4.x;
                sm[KOFF + (c * 4 + 1) * 136 + row] = v4.y;
                sm[KOFF + (c * 4 + 2) * 136 + row] = v4.z;
                sm[KOFF + (c * 4 + 3) * 136 + row] = v4.w;
            }
            __syncthreads();

            u64t acc[4][2];
#pragma unroll
            for (int r = 0; r < 4; r++) { acc[r][0] = 0ull; acc[r][1] = 0ull; }

#pragma unroll 4
            for (int kk = 0; kk < 64; kk++) {
                float4 a4 = *(const float4*)&sm[KOFF + kk * 136 + trn * 4];
                u64t a2[4] = { dup2(a4.x), dup2(a4.y), dup2(a4.z), dup2(a4.w) };
                u64t b0 = *(const u64t*)&sm[QOFF + kk * 68 + tcq * 4];
                u64t b1 = *(const u64t*)&sm[QOFF + kk * 68 + tcq * 4 + 2];
#pragma unroll
                for (int r = 0; r < 4; r++) { fma2(acc[r][0], a2[r], b0); fma2(acc[r][1], a2[r], b1); }
            }
#pragma unroll
            for (int r = 0; r < 4; r++) {
                int n = nt * 128 + trn * 4 + r;
                *(u64t*)&sm[n * SB_PAD + tcq * 4]     = mul2(acc[r][0], scale);
                *(u64t*)&sm[n * SB_PAD + tcq * 4 + 2] = mul2(acc[r][1], scale);
            }
        }
    }
    __syncthreads();

    // ---- Phase 2: softmax + attn writeback ----
    {
        const int warp = tid >> 5, lane = tid & 31;
        for (int qi = 0; qi < 4; qi++) {
            int ql = warp * 4 + qi;
            float m = -3.4e38f;
#pragma unroll
            for (int s = 0; s < 16; s++)
                m = fmaxf(m, sm[(lane + 32 * s) * SB_PAD + ql]);
#pragma unroll
            for (int off = 16; off >= 1; off >>= 1)
                m = fmaxf(m, __shfl_xor_sync(0xffffffffu, m, off));
            float sum = 0.f;
#pragma unroll
            for (int s = 0; s < 16; s++) {
                int n = lane + 32 * s;
                float e = __expf(sm[n * SB_PAD + ql] - m);
                sm[n * SB_PAD + ql] = e;
                sum += e;
            }
#pragma unroll
            for (int off = 16; off >= 1; off >>= 1)
                sum += __shfl_xor_sync(0xffffffffu, sum, off);
            float iv = 1.0f / sum;
            if (lane == 0) sm[IOFF + ql] = iv;
            float* drow = attn_out + ((size_t)hb * 512 + q0 + ql) * 512;
#pragma unroll
            for (int s = 0; s < 16; s++) {
                int n = lane + 32 * s;
                drow[n] = sm[n * SB_PAD + ql] * iv;
            }
        }
    }
    __syncthreads();

    // ---- Phase 3: O = P V ----
    {
        const int tdv = tid & 15;            // dv group of 4 (2 pairs)
        const int trq = (tid >> 4) & 7;      // q group of 8
        const int nh  = tid >> 7;            // n quarter 0..3

        u64t acc[8][2];
#pragma unroll
        for (int r = 0; r < 8; r++) { acc[r][0] = 0ull; acc[r][1] = 0ull; }

        for (int nt = 0; nt < 4; nt++) {
            __syncthreads();
            for (int f = tid; f < 2048; f += 512) {
                int row = f >> 4, c = f & 15;
                float4 v4 = *(const float4*)&g_vh[((size_t)hb * 512 + nt * 128 + row) * 64 + c * 4];
                *(float4*)&sm[KOFF + row * 68 + c * 4] = v4;
            }
            __syncthreads();

#pragma unroll 2
            for (int kk2 = 0; kk2 < 32; kk2++) {
                int kk = nh * 32 + kk2;
                int n = nt * 128 + kk;
                u64t b0 = *(const u64t*)&sm[KOFF + kk * 68 + tdv * 4];
                u64t b1 = *(const u64t*)&sm[KOFF + kk * 68 + tdv * 4 + 2];
#pragma unroll
                for (int r = 0; r < 8; r++) {
                    u64t a2 = dup2(sm[n * SB_PAD + trq * 8 + r]);
                    fma2(acc[r][0], a2, b0);
                    fma2(acc[r][1], a2, b1);
                }
            }
        }
        __syncthreads();   // S strip free now; use it for partial combine
        if (nh > 0) {
            int base = (nh - 1) * 4352 + (tid & 127) * 34;
#pragma unroll
            for (int r = 0; r < 8; r++) {
                *(u64t*)&sm[base + r * 4]     = acc[r][0];
                *(u64t*)&sm[base + r * 4 + 2] = acc[r][1];
            }
        }
        __syncthreads();
        if (nh == 0) {
            const int bb = hb & 15, hh = hb >> 4;
            int base = tid * 34;
#pragma unroll
            for (int r = 0; r < 8; r++) {
                u64t s0 = acc[r][0], s1 = acc[r][1];
#pragma unroll
                for (int p = 0; p < 3; p++) {
                    s0 = add2(s0, *(const u64t*)&sm[p * 4352 + base + r * 4]);
                    s1 = add2(s1, *(const u64t*)&sm[p * 4352 + base + r * 4 + 2]);
                }
                int ql = trq * 8 + r;
                u64t iv2 = dup2(sm[IOFF + ql]);
                float2 f0 = unp2(mul2(s0, iv2));
                float2 f1 = unp2(mul2(s1, iv2));
                float4 res = make_float4(f0.x, f0.y, f1.x, f1.y);
                *(float4*)&g_act[(((size_t)bb * 512 + q0 + ql) * 8 + hh) * 64 + tdv * 4] = res;
            }
        }
    }
}

// ===========================================================================
// FC: out[b][o] = sum_i act[b][i]*Wf[o][i], I=262144. 256-way split-K.
// ===========================================================================
#define FC_KC 1024
#define FC_SMEM_BYTES (8 * FC_KC * 8)    // 64 KB -> 2 blocks/SM

__global__ void __launch_bounds__(256, 2) fc_kernel(const float* __restrict__ Wf)
{
    extern __shared__ float2 sm2[];
    const int tid = threadIdx.x;
    const int k0 = blockIdx.x * FC_KC;
    const int o0 = blockIdx.y * 32;

    const float4* act4 = (const float4*)g_act;
    float* smf = (float*)sm2;
    for (int f = tid; f < 4096; f += 256) {
        int b = f >> 8, c = f & 255;
        float4 v = act4[(size_t)b * 65536 + (k0 >> 2) + c];
        int b2 = b >> 1, lo = b & 1;
        float* p = &smf[(b2 * FC_KC + c * 4) * 2 + lo];
        p[0] = v.x; p[2] = v.y; p[4] = v.z; p[6] = v.w;
    }
    __syncthreads();

    const int warp = tid >> 5, lane = tid & 31;
    const int ob = o0 + warp * 4;

    u64t acc[4][8];
#pragma unroll
    for (int j = 0; j < 4; j++)
#pragma unroll
        for (int b2 = 0; b2 < 8; b2++) acc[j][b2] = 0ull;

    const float* wr[4] = {
        Wf + (size_t)(ob + 0) * 262144 + k0, Wf + (size_t)(ob + 1) * 262144 + k0,
        Wf + (size_t)(ob + 2) * 262144 + k0, Wf + (size_t)(ob + 3) * 262144 + k0 };

    for (int i0 = lane * 4; i0 < FC_KC; i0 += 128) {
        float wv[4][4];
#pragma unroll
        for (int j = 0; j < 4; j++) {
            float4 w4 = *(const float4*)(wr[j] + i0);
            wv[j][0] = w4.x; wv[j][1] = w4.y; wv[j][2] = w4.z; wv[j][3] = w4.w;
        }
#pragma unroll
        for (int kk = 0; kk < 4; kk++) {
            u64t a[8];
#pragma unroll
            for (int b2 = 0; b2 < 8; b2++)
                a[b2] = *(const u64t*)&sm2[b2 * FC_KC + i0 + kk];
#pragma unroll
            for (int j = 0; j < 4; j++) {
                u64t wd = dup2(wv[j][kk]);
#pragma unroll
                for (int b2 = 0; b2 < 8; b2++)
                    fma2(acc[j][b2], wd, a[b2]);
            }
        }
    }

#pragma unroll
    for (int j = 0; j < 4; j++)
#pragma unroll
        for (int b2 = 0; b2 < 8; b2++) {
#pragma unroll
            for (int off = 16; off >= 1; off >>= 1) {
                u64t o = __shfl_down_sync(0xffffffffu, acc[j][b2], off);
                acc[j][b2] = add2(acc[j][b2], o);
            }
        }
    if (lane == 0) {
#pragma unroll
        for (int j = 0; j < 4; j++) {
            size_t base = ((size_t)blockIdx.x * 512 + ob + j) * 16;
#pragma unroll
            for (int b2 = 0; b2 < 8; b2++) {
                float2 f = unp2(acc[j][b2]);
                g_part[base + 2 * b2]     = f.x;
                g_part[base + 2 * b2 + 1] = f.y;
            }
        }
    }
}

__global__ void __launch_bounds__(256) reduce_fc(const float* __restrict__ bf,
                                                 float* __restrict__ out)
{
    __shared__ float red[8][33];
    const int t = threadIdx.x;
    const int oi = blockIdx.x * 32 + (t & 31);
    const int part = t >> 5;
    const int o = oi >> 4, b = oi & 15;
    float s = 0.f;
#pragma unroll 8
    for (int ks = part * 32; ks < part * 32 + 32; ks++)
        s += g_part[((size_t)ks * 512 + o) * 16 + b];
    red[part][t & 31] = s;
    __syncthreads();
    if (t < 32) {
        float tot = 0.f;
#pragma unroll
        for (int j = 0; j < 8; j++) tot += red[j][t];
        int oo = blockIdx.x * 32 + t;
        out[(oo & 15) * 512 + (oo >> 4)] = tot + bf[oo >> 4];
    }
}

// ===========================================================================
extern "C" void kernel_launch(void* const* d_in, const int* in_sizes, int n_in,
                              void* d_out, int out_size)
{
    const float* q  = (const float*)d_in[0];
    const float* k  = (const float*)d_in[1];
    const float* v  = (const float*)d_in[2];
    const float* Wq = (const float*)d_in[3];
    const float* bq = (const float*)d_in[4];
    const float* Wk = (const float*)d_in[5];
    const float* bk = (const float*)d_in[6];
    const float* Wv = (const float*)d_in[7];
    const float* bv = (const float*)d_in[8];
    const float* Wf = (const float*)d_in[9];
    const float* bf = (const float*)d_in[10];
    float* out = (float*)d_out;

    cudaFuncSetAttribute(proj_mma, cudaFuncAttributeMaxDynamicSharedMemorySize, PJ_SMEM);
    cudaFuncSetAttribute(attn_kernel, cudaFuncAttributeMaxDynamicSharedMemorySize,
                         ATTN_SMEM_BYTES);
    cudaFuncSetAttribute(fc_kernel, cudaFuncAttributeMaxDynamicSharedMemorySize,
                         FC_SMEM_BYTES);

    cvt_kernel<<<13056, 256>>>(q, k, v, Wq, Wk, Wv);
    proj_mma<<<dim3(4, 64, 3), 256, PJ_SMEM>>>(bq, bk, bv);
    attn_kernel<<<dim3(8, 128), 512, ATTN_SMEM_BYTES>>>(out + 8192);
    fc_kernel<<<dim3(256, 16), 256, FC_SMEM_BYTES>>>(Wf);
    reduce_fc<<<256, 256>>>(bf, out);
}

// round 7
// speedup vs baseline: 1.8216x; 1.0715x over previous
#include <cuda_runtime.h>
#include <cuda_bf16.h>
#include <cstdint>

// ---------------------------------------------------------------------------
// MultiHeadAttention: B=16, L=512, D=512, H=8, DK=DV=64, TEMP=8
// out = ( output[16,512], attn[128,512,512] ) concatenated in d_out (fp32)
// R6: R5 design with the fc swizzle weight-index fix (wv[j][kk], not kk^xv)
// ---------------------------------------------------------------------------

typedef unsigned long long u64t;

// ------------------------- scratch (static device mem) ---------------------
__device__ __align__(16) float g_qh[8 * 16 * 512 * 64];   // [h][b][l][d]
__device__ __align__(16) float g_kh[8 * 16 * 512 * 64];
__device__ __align__(16) float g_vh[8 * 16 * 512 * 64];
__device__ __align__(16) float g_act[16 * 512 * 512];     // [b][l][h][dv]
__device__ __align__(16) float g_part[256 * 512 * 16];    // [ksplit][o][b]
__device__ __align__(16) __nv_bfloat16 g_xhi[3 * 8192 * 512];
__device__ __align__(16) __nv_bfloat16 g_xlo[3 * 8192 * 512];
__device__ __align__(16) __nv_bfloat16 g_whi[3 * 512 * 512];
__device__ __align__(16) __nv_bfloat16 g_wlo[3 * 512 * 512];

// ------------------------- f32x2 helpers -----------------------------------
__device__ __forceinline__ u64t dup2(float x) {
    u64t r; asm("mov.b64 %0,{%1,%1};" : "=l"(r) : "f"(x)); return r;
}
__device__ __forceinline__ void fma2(u64t& d, u64t a, u64t b) {
    asm("fma.rn.f32x2 %0,%1,%2,%3;" : "=l"(d) : "l"(a), "l"(b), "l"(d));
}
__device__ __forceinline__ u64t add2(u64t a, u64t b) {
    u64t r; asm("add.rn.f32x2 %0,%1,%2;" : "=l"(r) : "l"(a), "l"(b)); return r;
}
__device__ __forceinline__ u64t mul2(u64t a, u64t b) {
    u64t r; asm("mul.rn.f32x2 %0,%1,%2;" : "=l"(r) : "l"(a), "l"(b)); return r;
}
__device__ __forceinline__ float2 unp2(u64t v) {
    float2 f; asm("mov.b64 {%0,%1},%2;" : "=f"(f.x), "=f"(f.y) : "l"(v)); return f;
}

// ------------------------- mma/ldmatrix/cp.async helpers --------------------
__device__ __forceinline__ uint32_t smem_u32(const void* p) {
    uint32_t a;
    asm("{ .reg .u64 t; cvta.to.shared.u64 t, %1; cvt.u32.u64 %0, t; }"
        : "=r"(a) : "l"(p));
    return a;
}
__device__ __forceinline__ void ldm4(uint32_t* r, uint32_t addr) {
    asm volatile("ldmatrix.sync.aligned.m8n8.x4.shared.b16 {%0,%1,%2,%3}, [%4];"
                 : "=r"(r[0]), "=r"(r[1]), "=r"(r[2]), "=r"(r[3]) : "r"(addr));
}
__device__ __forceinline__ void mma16816(float* c, const uint32_t* a,
                                         const uint32_t* b) {
    asm volatile(
        "mma.sync.aligned.m16n8k16.row.col.f32.bf16.bf16.f32 "
        "{%0,%1,%2,%3}, {%4,%5,%6,%7}, {%8,%9}, {%0,%1,%2,%3};"
        : "+f"(c[0]), "+f"(c[1]), "+f"(c[2]), "+f"(c[3])
        : "r"(a[0]), "r"(a[1]), "r"(a[2]), "r"(a[3]), "r"(b[0]), "r"(b[1]));
}
__device__ __forceinline__ void cpa16(uint32_t sa, const void* ga) {
    asm volatile("cp.async.cg.shared.global [%0], [%1], 16;"
                 :: "r"(sa), "l"(ga) : "memory");
}
__device__ __forceinline__ void cpa_commit() {
    asm volatile("cp.async.commit_group;" ::: "memory");
}
template <int N>
__device__ __forceinline__ void cpa_wait() {
    asm volatile("cp.async.wait_group %0;" :: "n"(N) : "memory");
}

// ===========================================================================
// cvt_kernel: fp32 -> (bf16 hi, bf16 lo) split for X (q,k,v) and W (Wq,Wk,Wv)
// ===========================================================================
__global__ void __launch_bounds__(256) cvt_kernel(
    const float* __restrict__ q, const float* __restrict__ k,
    const float* __restrict__ v,
    const float* __restrict__ Wq, const float* __restrict__ Wk,
    const float* __restrict__ Wv)
{
    const int t = blockIdx.x * 256 + threadIdx.x;       // one float4 per thread
    const int XN4 = 3 * 1048576;
    const int WN4 = 3 * 65536;
    if (t >= XN4 + WN4) return;

    const float* src;
    __nv_bfloat16 *dh, *dl;
    size_t off4;
    if (t < XN4) {
        int z = t >> 20, i = t & 1048575;
        src = (z == 0) ? q : (z == 1) ? k : v;
        dh = g_xhi + (size_t)z * 4194304; dl = g_xlo + (size_t)z * 4194304;
        off4 = i;
    } else {
        int t2 = t - XN4;
        int z = t2 >> 16, i = t2 & 65535;
        src = (z == 0) ? Wq : (z == 1) ? Wk : Wv;
        dh = g_whi + (size_t)z * 262144; dl = g_wlo + (size_t)z * 262144;
        off4 = i;
    }
    float4 x = *(const float4*)(src + off4 * 4);
    float a[4] = { x.x, x.y, x.z, x.w };
    __nv_bfloat16 h[4], l[4];
#pragma unroll
    for (int j = 0; j < 4; j++) {
        h[j] = __float2bfloat16(a[j]);
        l[j] = __float2bfloat16(a[j] - __bfloat162float(h[j]));
    }
    __nv_bfloat162* ph = (__nv_bfloat162*)(dh + off4 * 4);
    __nv_bfloat162* pl = (__nv_bfloat162*)(dl + off4 * 4);
    ph[0] = __halves2bfloat162(h[0], h[1]); ph[1] = __halves2bfloat162(h[2], h[3]);
    pl[0] = __halves2bfloat162(l[0], l[1]); pl[1] = __halves2bfloat162(l[2], l[3]);
}

// ===========================================================================
// proj_mma: mma.sync bf16 split-2 GEMM. CTA tile M=128, N=128, K=512,
// K-chunk 64 double-buffered via cp.async. 8 warps, warp tile 32x64.
// ===========================================================================
#define RS     144                 // smem row stride bytes (72 halves, padded)
#define MHALF  18432               // one 128x64 bf16 matrix (padded)
#define CH_BUF 73728               // A_hi + A_lo + B_hi + B_lo
#define PJ_SMEM (2 * CH_BUF)

__global__ void __launch_bounds__(256) proj_mma(
    const float* __restrict__ bq, const float* __restrict__ bk,
    const float* __restrict__ bv)
{
    extern __shared__ char smem[];
    const uint32_t sb = smem_u32(smem);
    const int tid = threadIdx.x;
    const int wid = tid >> 5, lane = tid & 31;
    const int warp_m = wid & 3, warp_n = wid >> 2;     // 4x2 warp grid

    const int z = blockIdx.z;
    const int m0 = blockIdx.y * 128;
    const int n0 = blockIdx.x * 128;
    const float* bias = (z == 0) ? bq : (z == 1) ? bk : bv;
    float* dst = (z == 0) ? g_qh : (z == 1) ? g_kh : g_vh;

    const __nv_bfloat16* gm[4] = {
        g_xhi + ((size_t)z * 8192 + m0) * 512,
        g_xlo + ((size_t)z * 8192 + m0) * 512,
        g_whi + ((size_t)z * 512 + n0) * 512,
        g_wlo + ((size_t)z * 512 + n0) * 512 };

    const uint32_t a_row  = lane & 15;
    const uint32_t a_koff = (lane >> 4) * 8;
    const uint32_t b_nrow = ((lane >> 4) * 8) + (lane & 7);
    const uint32_t b_koff = ((lane >> 3) & 1) * 8;

    float acc[2][8][4];
#pragma unroll
    for (int mt = 0; mt < 2; mt++)
#pragma unroll
        for (int nt = 0; nt < 8; nt++)
#pragma unroll
            for (int j = 0; j < 4; j++) acc[mt][nt][j] = 0.f;

    auto load_chunk = [&](int c) {
        const int kc = c * 64;
        const uint32_t base = sb + (uint32_t)(c & 1) * CH_BUF;
#pragma unroll
        for (int mat = 0; mat < 4; mat++) {
            const __nv_bfloat16* g = gm[mat];
#pragma unroll
            for (int i = 0; i < 4; i++) {
                int idx = tid + i * 256;
                int row = idx >> 3, seg = idx & 7;
                cpa16(base + mat * MHALF + row * RS + seg * 16,
                      g + (size_t)row * 512 + kc + seg * 8);
            }
        }
        cpa_commit();
    };

    load_chunk(0);
    load_chunk(1);

    for (int c = 0; c < 8; c++) {
        if (c < 7) cpa_wait<1>(); else cpa_wait<0>();
        __syncthreads();

        const uint32_t bufb = sb + (uint32_t)(c & 1) * CH_BUF;
        const uint32_t aBase = bufb + (warp_m * 32 + a_row) * RS + a_koff * 2;
        const uint32_t bBase = bufb + 2 * MHALF +
                               (warp_n * 64 + b_nrow) * RS + b_koff * 2;
#pragma unroll
        for (int ks = 0; ks < 4; ks++) {
            uint32_t aH[2][4], aL[2][4], bH[8][2], bL[8][2];
#pragma unroll
            for (int mt = 0; mt < 2; mt++) {
                uint32_t ad = aBase + mt * 16 * RS + ks * 32;
                ldm4(aH[mt], ad);
                ldm4(aL[mt], ad + MHALF);
            }
#pragma unroll
            for (int nb = 0; nb < 4; nb++) {
                uint32_t bd = bBase + nb * 16 * RS + ks * 32;
                uint32_t r[4];
                ldm4(r, bd);
                bH[2 * nb][0] = r[0]; bH[2 * nb][1] = r[1];
                bH[2 * nb + 1][0] = r[2]; bH[2 * nb + 1][1] = r[3];
                ldm4(r, bd + MHALF);
                bL[2 * nb][0] = r[0]; bL[2 * nb][1] = r[1];
                bL[2 * nb + 1][0] = r[2]; bL[2 * nb + 1][1] = r[3];
            }
#pragma unroll
            for (int mt = 0; mt < 2; mt++)
#pragma unroll
                for (int nt = 0; nt < 8; nt++) {
                    mma16816(acc[mt][nt], aH[mt], bH[nt]);
                    mma16816(acc[mt][nt], aH[mt], bL[nt]);
                    mma16816(acc[mt][nt], aL[mt], bH[nt]);
                }
        }
        __syncthreads();
        if (c + 2 < 8) load_chunk(c + 2);
    }

    // epilogue: regs -> smem stage (pad 132) -> coalesced global
    float* stage = (float*)smem;
#pragma unroll
    for (int mt = 0; mt < 2; mt++)
#pragma unroll
        for (int nt = 0; nt < 8; nt++) {
            int row = warp_m * 32 + mt * 16 + (lane >> 2);
            int col = warp_n * 64 + nt * 8 + (lane & 3) * 2;
            *(float2*)&stage[row * 132 + col] =
                make_float2(acc[mt][nt][0], acc[mt][nt][1]);
            *(float2*)&stage[(row + 8) * 132 + col] =
                make_float2(acc[mt][nt][2], acc[mt][nt][3]);
        }
    __syncthreads();

    for (int f = tid; f < 4096; f += 256) {
        int row = f >> 5, c4 = f & 31;
        int nn = c4 * 4;
        int rg = m0 + row, bb = rg >> 9, ll = rg & 511;
        int hh = (n0 + nn) >> 6, d = nn & 63;
        float4 r;
        r.x = stage[row * 132 + nn + 0] + __ldg(&bias[n0 + nn + 0]);
        r.y = stage[row * 132 + nn + 1] + __ldg(&bias[n0 + nn + 1]);
        r.z = stage[row * 132 + nn + 2] + __ldg(&bias[n0 + nn + 2]);
        r.w = stage[row * 132 + nn + 3] + __ldg(&bias[n0 + nn + 3]);
        *(float4*)&dst[(((size_t)hh * 16 + bb) * 512 + ll) * 64 + d] = r;
    }
}

// ===========================================================================
// Attention kernel: CTA per (hb, qtile 64). 512 threads (16 warps).
// S strip q-major: S[q][n], row stride SP=520. Softmax/writeback vectorized.
// ===========================================================================
#define SP     520
#define SB_SZ  (64 * SP)                 // 33280 floats
#define QOFF   SB_SZ
#define KOFF   (QOFF + 64 * 68)          // 37632
#define IOFF   (KOFF + 8704)             // 46336
#define ATTN_SMEM_BYTES  ((IOFF + 64) * 4)

__global__ void __launch_bounds__(512) attn_kernel(float* __restrict__ attn_out)
{
    extern __shared__ float sm[];
    const int tid = threadIdx.x;
    const int hb = blockIdx.y;
    const int q0 = blockIdx.x * 64;

    // Q tile transposed: Qs[d][q] pad 68
    for (int f = tid; f < 1024; f += 512) {
        int row = f >> 4, c = f & 15;
        float4 v4 = *(const float4*)&g_qh[((size_t)hb * 512 + q0 + row) * 64 + c * 4];
        sm[QOFF + (c * 4 + 0) * 68 + row] = v4.x;
        sm[QOFF + (c * 4 + 1) * 68 + row] = v4.y;
        sm[QOFF + (c * 4 + 2) * 68 + row] = v4.z;
        sm[QOFF + (c * 4 + 3) * 68 + row] = v4.w;
    }

    // ---- Phase 1: QK^T -> S[q][n] ----
    {
        const int trn = tid & 31;
        const int tcq = tid >> 5;            // warp id: 16 q-groups of 4
        const u64t scale = dup2(0.125f);

        for (int nt = 0; nt < 4; nt++) {
            __syncthreads();
            for (int f = tid; f < 2048; f += 512) {
                int row = f >> 4, c = f & 15;
                float4 v4 = *(const float4*)&g_kh[((size_t)hb * 512 + nt * 128 + row) * 64 + c * 4];
                sm[KOFF + (c * 4 + 0) * 136 + row] = v4.x;
                sm[KOFF + (c * 4 + 1) * 136 + row] = v4.y;
                sm[KOFF + (c * 4 + 2) * 136 + row] = v4.z;
                sm[KOFF + (c * 4 + 3) * 136 + row] = v4.w;
            }
            __syncthreads();

            u64t acc[4][2];
#pragma unroll
            for (int r = 0; r < 4; r++) { acc[r][0] = 0ull; acc[r][1] = 0ull; }

#pragma unroll 4
            for (int kk = 0; kk < 64; kk++) {
                float4 a4 = *(const float4*)&sm[KOFF + kk * 136 + trn * 4];
                u64t a2[4] = { dup2(a4.x), dup2(a4.y), dup2(a4.z), dup2(a4.w) };
                u64t b0 = *(const u64t*)&sm[QOFF + kk * 68 + tcq * 4];
                u64t b1 = *(const u64t*)&sm[QOFF + kk * 68 + tcq * 4 + 2];
#pragma unroll
                for (int r = 0; r < 4; r++) { fma2(acc[r][0], a2[r], b0); fma2(acc[r][1], a2[r], b1); }
            }
            // transposed scalar stores into q-major strip (4-way, one pass)
#pragma unroll
            for (int r = 0; r < 4; r++) {
                int n = nt * 128 + trn * 4 + r;
                float2 s0 = unp2(mul2(acc[r][0], scale));
                float2 s1 = unp2(mul2(acc[r][1], scale));
                sm[(tcq * 4 + 0) * SP + n] = s0.x;
                sm[(tcq * 4 + 1) * SP + n] = s0.y;
                sm[(tcq * 4 + 2) * SP + n] = s1.x;
                sm[(tcq * 4 + 3) * SP + n] = s1.y;
            }
        }
    }
    __syncthreads();

    // ---- Phase 2: softmax rows (vectorized, conflict-free) + writeback ----
    {
        const int warp = tid >> 5, lane = tid & 31;
        for (int qi = 0; qi < 4; qi++) {
            int ql = warp * 4 + qi;
            float* srow = &sm[ql * SP];
            float m = -3.4e38f;
#pragma unroll
            for (int s = 0; s < 4; s++) {
                float4 v = *(const float4*)&srow[(s * 32 + lane) * 4];
                m = fmaxf(m, fmaxf(fmaxf(v.x, v.y), fmaxf(v.z, v.w)));
            }
#pragma unroll
            for (int off = 16; off >= 1; off >>= 1)
                m = fmaxf(m, __shfl_xor_sync(0xffffffffu, m, off));
            float sum = 0.f;
#pragma unroll
            for (int s = 0; s < 4; s++) {
                float4* p = (float4*)&srow[(s * 32 + lane) * 4];
                float4 v = *p;
                v.x = __expf(v.x - m); v.y = __expf(v.y - m);
                v.z = __expf(v.z - m); v.w = __expf(v.w - m);
                *p = v;
                sum += v.x + v.y + v.z + v.w;
            }
#pragma unroll
            for (int off = 16; off >= 1; off >>= 1)
                sum += __shfl_xor_sync(0xffffffffu, sum, off);
            float iv = 1.0f / sum;
            if (lane == 0) sm[IOFF + ql] = iv;
            float* drow = attn_out + ((size_t)hb * 512 + q0 + ql) * 512;
#pragma unroll
            for (int s = 0; s < 4; s++) {
                float4 v = *(const float4*)&srow[(s * 32 + lane) * 4];
                v.x *= iv; v.y *= iv; v.z *= iv; v.w *= iv;
                *(float4*)&drow[(s * 32 + lane) * 4] = v;
            }
        }
    }
    __syncthreads();

    // ---- Phase 3: O = P V ----
    {
        const int tdv = tid & 15;            // dv group of 4 (2 pairs)
        const int trq = (tid >> 4) & 7;      // interleaved q sub-index
        const int nh  = tid >> 7;            // n quarter 0..3

        u64t acc[8][2];
#pragma unroll
        for (int r = 0; r < 8; r++) { acc[r][0] = 0ull; acc[r][1] = 0ull; }

        for (int nt = 0; nt < 4; nt++) {
            __syncthreads();
            for (int f = tid; f < 2048; f += 512) {
                int row = f >> 4, c = f & 15;
                float4 v4 = *(const float4*)&g_vh[((size_t)hb * 512 + nt * 128 + row) * 64 + c * 4];
                *(float4*)&sm[KOFF + row * 68 + c * 4] = v4;
            }
            __syncthreads();

#pragma unroll 2
            for (int kk2 = 0; kk2 < 32; kk2++) {
                int kk = nh * 32 + kk2;
                int n = nt * 128 + kk;
                u64t b0 = *(const u64t*)&sm[KOFF + kk * 68 + tdv * 4];
                u64t b1 = *(const u64t*)&sm[KOFF + kk * 68 + tdv * 4 + 2];
#pragma unroll
                for (int r = 0; r < 8; r++) {
                    u64t a2 = dup2(sm[(r * 8 + trq) * SP + n]);
                    fma2(acc[r][0], a2, b0);
                    fma2(acc[r][1], a2, b1);
                }
            }
        }
        __syncthreads();   // S strip free now; use it for partial combine
        if (nh > 0) {
            int base = (nh - 1) * 4352 + (tid & 127) * 34;
#pragma unroll
            for (int r = 0; r < 8; r++) {
                *(u64t*)&sm[base + r * 4]     = acc[r][0];
                *(u64t*)&sm[base + r * 4 + 2] = acc[r][1];
            }
        }
        __syncthreads();
        if (nh == 0) {
            const int bb = hb & 15, hh = hb >> 4;
            int base = tid * 34;
#pragma unroll
            for (int r = 0; r < 8; r++) {
                u64t s0 = acc[r][0], s1 = acc[r][1];
#pragma unroll
                for (int p = 0; p < 3; p++) {
                    s0 = add2(s0, *(const u64t*)&sm[p * 4352 + base + r * 4]);
                    s1 = add2(s1, *(const u64t*)&sm[p * 4352 + base + r * 4 + 2]);
                }
                int ql = r * 8 + trq;
                u64t iv2 = dup2(sm[IOFF + ql]);
                float2 f0 = unp2(mul2(s0, iv2));
                float2 f1 = unp2(mul2(s1, iv2));
                float4 res = make_float4(f0.x, f0.y, f1.x, f1.y);
                *(float4*)&g_act[(((size_t)bb * 512 + q0 + ql) * 8 + hh) * 64 + tdv * 4] = res;
            }
        }
    }
}

// ===========================================================================
// FC: out[b][o] = sum_i act[b][i]*Wf[o][i], I=262144. 256-way split-K.
// Act staged with XOR swizzle: logical float2 k at physical
// (k&~3)|((k&3)^((k>>4)&3)). Read at physical i0+(kk^xv) (xv=(i0>>4)&3)
// yields LOGICAL i0+kk -> pair with weight wv[j][kk].   (R6 fix)
// ===========================================================================
#define FC_KC 1024
#define FC_SMEM_BYTES (8 * FC_KC * 8)    // 64 KB -> 2 blocks/SM

__global__ void __launch_bounds__(256, 2) fc_kernel(const float* __restrict__ Wf)
{
    extern __shared__ float2 sm2[];
    const int tid = threadIdx.x;
    const int k0 = blockIdx.x * FC_KC;
    const int o0 = blockIdx.y * 32;

    const float4* act4 = (const float4*)g_act;
    float* smf = (float*)sm2;
    for (int f = tid; f < 4096; f += 256) {
        int b = f >> 8, c = f & 255;
        float4 v = act4[(size_t)b * 65536 + (k0 >> 2) + c];
        int b2 = b >> 1, lo = b & 1;
        int cx = (c >> 2) & 3;                     // swizzle bits = (k>>4)&3
        int base = b2 * FC_KC + c * 4;
        smf[2 * (base + (0 ^ cx)) + lo] = v.x;
        smf[2 * (base + (1 ^ cx)) + lo] = v.y;
        smf[2 * (base + (2 ^ cx)) + lo] = v.z;
        smf[2 * (base + (3 ^ cx)) + lo] = v.w;
    }
    __syncthreads();

    const int warp = tid >> 5, lane = tid & 31;
    const int ob = o0 + warp * 4;
    const int xv = (lane >> 2) & 3;                // read-side swizzle constant

    u64t acc[4][8];
#pragma unroll
    for (int j = 0; j < 4; j++)
#pragma unroll
        for (int b2 = 0; b2 < 8; b2++) acc[j][b2] = 0ull;

    const float* wr[4] = {
        Wf + (size_t)(ob + 0) * 262144 + k0, Wf + (size_t)(ob + 1) * 262144 + k0,
        Wf + (size_t)(ob + 2) * 262144 + k0, Wf + (size_t)(ob + 3) * 262144 + k0 };

    for (int i0 = lane * 4; i0 < FC_KC; i0 += 128) {
        float wv[4][4];
#pragma unroll
        for (int j = 0; j < 4; j++) {
            float4 w4 = *(const float4*)(wr[j] + i0);
            wv[j][0] = w4.x; wv[j][1] = w4.y; wv[j][2] = w4.z; wv[j][3] = w4.w;
        }
#pragma unroll
        for (int kk = 0; kk < 4; kk++) {
            const int ik = i0 + (kk ^ xv);         // physical slot
            u64t a[8];
#pragma unroll
            for (int b2 = 0; b2 < 8; b2++)
                a[b2] = *(const u64t*)&sm2[b2 * FC_KC + ik];
#pragma unroll
            for (int j = 0; j < 4; j++) {
                u64t wd = dup2(wv[j][kk]);         // logical k = i0 + kk  (FIX)
#pragma unroll
                for (int b2 = 0; b2 < 8; b2++)
                    fma2(acc[j][b2], wd, a[b2]);
            }
        }
    }

#pragma unroll
    for (int j = 0; j < 4; j++)
#pragma unroll
        for (int b2 = 0; b2 < 8; b2++) {
#pragma unroll
            for (int off = 16; off >= 1; off >>= 1) {
                u64t o = __shfl_down_sync(0xffffffffu, acc[j][b2], off);
                acc[j][b2] = add2(acc[j][b2], o);
            }
        }
    if (lane == 0) {
#pragma unroll
        for (int j = 0; j < 4; j++) {
            size_t base = ((size_t)blockIdx.x * 512 + ob + j) * 16;
#pragma unroll
            for (int b2 = 0; b2 < 8; b2++) {
                float2 f = unp2(acc[j][b2]);
                g_part[base + 2 * b2]     = f.x;
                g_part[base + 2 * b2 + 1] = f.y;
            }
        }
    }
}

__global__ void __launch_bounds__(256) reduce_fc(const float* __restrict__ bf,
                                                 float* __restrict__ out)
{
    __shared__ float red[8][33];
    const int t = threadIdx.x;
    const int oi = blockIdx.x * 32 + (t & 31);
    const int part = t >> 5;
    const int o = oi >> 4, b = oi & 15;
    float s = 0.f;
#pragma unroll 8
    for (int ks = part * 32; ks < part * 32 + 32; ks++)
        s += g_part[((size_t)ks * 512 + o) * 16 + b];
    red[part][t & 31] = s;
    __syncthreads();
    if (t < 32) {
        float tot = 0.f;
#pragma unroll
        for (int j = 0; j < 8; j++) tot += red[j][t];
        int oo = blockIdx.x * 32 + t;
        out[(oo & 15) * 512 + (oo >> 4)] = tot + bf[oo >> 4];
    }
}

// ===========================================================================
extern "C" void kernel_launch(void* const* d_in, const int* in_sizes, int n_in,
                              void* d_out, int out_size)
{
    const float* q  = (const float*)d_in[0];
    const float* k  = (const float*)d_in[1];
    const float* v  = (const float*)d_in[2];
    const float* Wq = (const float*)d_in[3];
    const float* bq = (const float*)d_in[4];
    const float* Wk = (const float*)d_in[5];
    const float* bk = (const float*)d_in[6];
    const float* Wv = (const float*)d_in[7];
    const float* bv = (const float*)d_in[8];
    const float* Wf = (const float*)d_in[9];
    const float* bf = (const float*)d_in[10];
    float* out = (float*)d_out;

    cudaFuncSetAttribute(proj_mma, cudaFuncAttributeMaxDynamicSharedMemorySize, PJ_SMEM);
    cudaFuncSetAttribute(attn_kernel, cudaFuncAttributeMaxDynamicSharedMemorySize,
                         ATTN_SMEM_BYTES);
    cudaFuncSetAttribute(fc_kernel, cudaFuncAttributeMaxDynamicSharedMemorySize,
                         FC_SMEM_BYTES);

    cvt_kernel<<<13056, 256>>>(q, k, v, Wq, Wk, Wv);
    proj_mma<<<dim3(4, 64, 3), 256, PJ_SMEM>>>(bq, bk, bv);
    attn_kernel<<<dim3(8, 128), 512, ATTN_SMEM_BYTES>>>(out + 8192);
    fc_kernel<<<dim3(256, 16), 256, FC_SMEM_BYTES>>>(Wf);
    reduce_fc<<<256, 256>>>(bf, out);
}

// round 8
// speedup vs baseline: 2.6077x; 1.4316x over previous
#include <cuda_runtime.h>
#include <cuda_bf16.h>
#include <cstdint>

// ---------------------------------------------------------------------------
// MultiHeadAttention: B=16, L=512, D=512, H=8, DK=DV=64, TEMP=8
// out = ( output[16,512], attn[128,512,512] ) concatenated in d_out (fp32)
// R7: mma.sync bf16-split for QK^T and PV (attn v2); proj emits bf16 hi/lo
// ---------------------------------------------------------------------------

typedef unsigned long long u64t;

// ------------------------- scratch (static device mem) ---------------------
__device__ __align__(16) float g_act[16 * 512 * 512];     // [b][l][h][dv]
__device__ __align__(16) float g_part[256 * 512 * 16];    // [ksplit][o][b]
__device__ __align__(16) __nv_bfloat16 g_xhi[3 * 8192 * 512];
__device__ __align__(16) __nv_bfloat16 g_xlo[3 * 8192 * 512];
__device__ __align__(16) __nv_bfloat16 g_whi[3 * 512 * 512];
__device__ __align__(16) __nv_bfloat16 g_wlo[3 * 512 * 512];
// head-major bf16 hi/lo projections: [h*16+b][l][64]
__device__ __align__(16) __nv_bfloat16 g_qBh[128 * 512 * 64];
__device__ __align__(16) __nv_bfloat16 g_qBl[128 * 512 * 64];
__device__ __align__(16) __nv_bfloat16 g_kBh[128 * 512 * 64];
__device__ __align__(16) __nv_bfloat16 g_kBl[128 * 512 * 64];
__device__ __align__(16) __nv_bfloat16 g_vBh[128 * 512 * 64];
__device__ __align__(16) __nv_bfloat16 g_vBl[128 * 512 * 64];

// ------------------------- f32x2 helpers (fc kernel) ------------------------
__device__ __forceinline__ u64t dup2(float x) {
    u64t r; asm("mov.b64 %0,{%1,%1};" : "=l"(r) : "f"(x)); return r;
}
__device__ __forceinline__ void fma2(u64t& d, u64t a, u64t b) {
    asm("fma.rn.f32x2 %0,%1,%2,%3;" : "=l"(d) : "l"(a), "l"(b), "l"(d));
}
__device__ __forceinline__ u64t add2(u64t a, u64t b) {
    u64t r; asm("add.rn.f32x2 %0,%1,%2;" : "=l"(r) : "l"(a), "l"(b)); return r;
}
__device__ __forceinline__ float2 unp2(u64t v) {
    float2 f; asm("mov.b64 {%0,%1},%2;" : "=f"(f.x), "=f"(f.y) : "l"(v)); return f;
}

// ------------------------- mma/ldmatrix/cp.async helpers --------------------
__device__ __forceinline__ uint32_t smem_u32(const void* p) {
    uint32_t a;
    asm("{ .reg .u64 t; cvta.to.shared.u64 t, %1; cvt.u32.u64 %0, t; }"
        : "=r"(a) : "l"(p));
    return a;
}
__device__ __forceinline__ void ldm4(uint32_t* r, uint32_t addr) {
    asm volatile("ldmatrix.sync.aligned.m8n8.x4.shared.b16 {%0,%1,%2,%3}, [%4];"
                 : "=r"(r[0]), "=r"(r[1]), "=r"(r[2]), "=r"(r[3]) : "r"(addr));
}
__device__ __forceinline__ void ldm4t(uint32_t* r, uint32_t addr) {
    asm volatile("ldmatrix.sync.aligned.m8n8.x4.trans.shared.b16 {%0,%1,%2,%3}, [%4];"
                 : "=r"(r[0]), "=r"(r[1]), "=r"(r[2]), "=r"(r[3]) : "r"(addr));
}
__device__ __forceinline__ void mma16816(float* c, const uint32_t* a,
                                         const uint32_t* b) {
    asm volatile(
        "mma.sync.aligned.m16n8k16.row.col.f32.bf16.bf16.f32 "
        "{%0,%1,%2,%3}, {%4,%5,%6,%7}, {%8,%9}, {%0,%1,%2,%3};"
        : "+f"(c[0]), "+f"(c[1]), "+f"(c[2]), "+f"(c[3])
        : "r"(a[0]), "r"(a[1]), "r"(a[2]), "r"(a[3]), "r"(b[0]), "r"(b[1]));
}
__device__ __forceinline__ void cpa16(uint32_t sa, const void* ga) {
    asm volatile("cp.async.cg.shared.global [%0], [%1], 16;"
                 :: "r"(sa), "l"(ga) : "memory");
}
__device__ __forceinline__ void cpa_commit() {
    asm volatile("cp.async.commit_group;" ::: "memory");
}
template <int N>
__device__ __forceinline__ void cpa_wait() {
    asm volatile("cp.async.wait_group %0;" :: "n"(N) : "memory");
}

// ===========================================================================
// cvt_kernel: fp32 -> (bf16 hi, bf16 lo) split for X (q,k,v) and W (Wq,Wk,Wv)
// ===========================================================================
__global__ void __launch_bounds__(256) cvt_kernel(
    const float* __restrict__ q, const float* __restrict__ k,
    const float* __restrict__ v,
    const float* __restrict__ Wq, const float* __restrict__ Wk,
    const float* __restrict__ Wv)
{
    const int t = blockIdx.x * 256 + threadIdx.x;
    const int XN4 = 3 * 1048576;
    const int WN4 = 3 * 65536;
    if (t >= XN4 + WN4) return;

    const float* src;
    __nv_bfloat16 *dh, *dl;
    size_t off4;
    if (t < XN4) {
        int z = t >> 20, i = t & 1048575;
        src = (z == 0) ? q : (z == 1) ? k : v;
        dh = g_xhi + (size_t)z * 4194304; dl = g_xlo + (size_t)z * 4194304;
        off4 = i;
    } else {
        int t2 = t - XN4;
        int z = t2 >> 16, i = t2 & 65535;
        src = (z == 0) ? Wq : (z == 1) ? Wk : Wv;
        dh = g_whi + (size_t)z * 262144; dl = g_wlo + (size_t)z * 262144;
        off4 = i;
    }
    float4 x = *(const float4*)(src + off4 * 4);
    float a[4] = { x.x, x.y, x.z, x.w };
    __nv_bfloat16 h[4], l[4];
#pragma unroll
    for (int j = 0; j < 4; j++) {
        h[j] = __float2bfloat16(a[j]);
        l[j] = __float2bfloat16(a[j] - __bfloat162float(h[j]));
    }
    __nv_bfloat162* ph = (__nv_bfloat162*)(dh + off4 * 4);
    __nv_bfloat162* pl = (__nv_bfloat162*)(dl + off4 * 4);
    ph[0] = __halves2bfloat162(h[0], h[1]); ph[1] = __halves2bfloat162(h[2], h[3]);
    pl[0] = __halves2bfloat162(l[0], l[1]); pl[1] = __halves2bfloat162(l[2], l[3]);
}

// ===========================================================================
// proj_mma: mma.sync bf16 split-2 GEMM. CTA tile M=128, N=128, K=512.
// Epilogue emits bf16 hi/lo head-major projections (fp32 + bias split fresh).
// ===========================================================================
#define RS     144
#define MHALF  18432
#define CH_BUF 73728
#define PJ_SMEM (2 * CH_BUF)

__global__ void __launch_bounds__(256) proj_mma(
    const float* __restrict__ bq, const float* __restrict__ bk,
    const float* __restrict__ bv)
{
    extern __shared__ char smem[];
    const uint32_t sb = smem_u32(smem);
    const int tid = threadIdx.x;
    const int wid = tid >> 5, lane = tid & 31;
    const int warp_m = wid & 3, warp_n = wid >> 2;

    const int z = blockIdx.z;
    const int m0 = blockIdx.y * 128;
    const int n0 = blockIdx.x * 128;
    const float* bias = (z == 0) ? bq : (z == 1) ? bk : bv;
    __nv_bfloat16* dH = (z == 0) ? g_qBh : (z == 1) ? g_kBh : g_vBh;
    __nv_bfloat16* dL = (z == 0) ? g_qBl : (z == 1) ? g_kBl : g_vBl;

    const __nv_bfloat16* gm[4] = {
        g_xhi + ((size_t)z * 8192 + m0) * 512,
        g_xlo + ((size_t)z * 8192 + m0) * 512,
        g_whi + ((size_t)z * 512 + n0) * 512,
        g_wlo + ((size_t)z * 512 + n0) * 512 };

    const uint32_t a_row  = lane & 15;
    const uint32_t a_koff = (lane >> 4) * 8;
    const uint32_t b_nrow = ((lane >> 4) * 8) + (lane & 7);
    const uint32_t b_koff = ((lane >> 3) & 1) * 8;

    float acc[2][8][4];
#pragma unroll
    for (int mt = 0; mt < 2; mt++)
#pragma unroll
        for (int nt = 0; nt < 8; nt++)
#pragma unroll
            for (int j = 0; j < 4; j++) acc[mt][nt][j] = 0.f;

    auto load_chunk = [&](int c) {
        const int kc = c * 64;
        const uint32_t base = sb + (uint32_t)(c & 1) * CH_BUF;
#pragma unroll
        for (int mat = 0; mat < 4; mat++) {
            const __nv_bfloat16* g = gm[mat];
#pragma unroll
            for (int i = 0; i < 4; i++) {
                int idx = tid + i * 256;
                int row = idx >> 3, seg = idx & 7;
                cpa16(base + mat * MHALF + row * RS + seg * 16,
                      g + (size_t)row * 512 + kc + seg * 8);
            }
        }
        cpa_commit();
    };

    load_chunk(0);
    load_chunk(1);

    for (int c = 0; c < 8; c++) {
        if (c < 7) cpa_wait<1>(); else cpa_wait<0>();
        __syncthreads();

        const uint32_t bufb = sb + (uint32_t)(c & 1) * CH_BUF;
        const uint32_t aBase = bufb + (warp_m * 32 + a_row) * RS + a_koff * 2;
        const uint32_t bBase = bufb + 2 * MHALF +
                               (warp_n * 64 + b_nrow) * RS + b_koff * 2;
#pragma unroll
        for (int ks = 0; ks < 4; ks++) {
            uint32_t aH[2][4], aL[2][4], bH[8][2], bL[8][2];
#pragma unroll
            for (int mt = 0; mt < 2; mt++) {
                uint32_t ad = aBase + mt * 16 * RS + ks * 32;
                ldm4(aH[mt], ad);
                ldm4(aL[mt], ad + MHALF);
            }
#pragma unroll
            for (int nb = 0; nb < 4; nb++) {
                uint32_t bd = bBase + nb * 16 * RS + ks * 32;
                uint32_t r[4];
                ldm4(r, bd);
                bH[2 * nb][0] = r[0]; bH[2 * nb][1] = r[1];
                bH[2 * nb + 1][0] = r[2]; bH[2 * nb + 1][1] = r[3];
                ldm4(r, bd + MHALF);
                bL[2 * nb][0] = r[0]; bL[2 * nb][1] = r[1];
                bL[2 * nb + 1][0] = r[2]; bL[2 * nb + 1][1] = r[3];
            }
#pragma unroll
            for (int mt = 0; mt < 2; mt++)
#pragma unroll
                for (int nt = 0; nt < 8; nt++) {
                    mma16816(acc[mt][nt], aH[mt], bH[nt]);
                    mma16816(acc[mt][nt], aH[mt], bL[nt]);
                    mma16816(acc[mt][nt], aL[mt], bH[nt]);
                }
        }
        __syncthreads();
        if (c + 2 < 8) load_chunk(c + 2);
    }

    // epilogue: regs -> smem stage (pad 132) -> bf16 hi/lo coalesced stores
    float* stage = (float*)smem;
#pragma unroll
    for (int mt = 0; mt < 2; mt++)
#pragma unroll
        for (int nt = 0; nt < 8; nt++) {
            int row = warp_m * 32 + mt * 16 + (lane >> 2);
            int col = warp_n * 64 + nt * 8 + (lane & 3) * 2;
            *(float2*)&stage[row * 132 + col] =
                make_float2(acc[mt][nt][0], acc[mt][nt][1]);
            *(float2*)&stage[(row + 8) * 132 + col] =
                make_float2(acc[mt][nt][2], acc[mt][nt][3]);
        }
    __syncthreads();

    for (int f = tid; f < 4096; f += 256) {
        int row = f >> 5, c4 = f & 31;
        int nn = c4 * 4;
        int rg = m0 + row, bbi = rg >> 9, ll = rg & 511;
        int hh2 = (n0 + nn) >> 6, d = nn & 63;
        float r[4];
#pragma unroll
        for (int j = 0; j < 4; j++)
            r[j] = stage[row * 132 + nn + j] + __ldg(&bias[n0 + nn + j]);
        __nv_bfloat16 h[4], l[4];
#pragma unroll
        for (int j = 0; j < 4; j++) {
            h[j] = __float2bfloat16(r[j]);
            l[j] = __float2bfloat16(r[j] - __bfloat162float(h[j]));
        }
        size_t off = (((size_t)hh2 * 16 + bbi) * 512 + ll) * 64 + d;
        __nv_bfloat162 hp0 = __halves2bfloat162(h[0], h[1]);
        __nv_bfloat162 hp1 = __halves2bfloat162(h[2], h[3]);
        __nv_bfloat162 lp0 = __halves2bfloat162(l[0], l[1]);
        __nv_bfloat162 lp1 = __halves2bfloat162(l[2], l[3]);
        uint2 uh, ul;
        uh.x = *(uint32_t*)&hp0; uh.y = *(uint32_t*)&hp1;
        ul.x = *(uint32_t*)&lp0; ul.y = *(uint32_t*)&lp1;
        *(uint2*)&dH[off] = uh;
        *(uint2*)&dL[off] = ul;
    }
}

// ===========================================================================
// attn v2: CTA per (hb, qtile 64), 256 threads (8 warps), mma.sync both GEMMs.
// smem (bytes): [0,133120) S strip 64x520 fp32
//               [133120,151552) Q hi/lo bf16 64x64 (rows 144B)
//               [151552,225280) multiuse: ph1 K dbl-buf 2x36864;
//                               ph3 P hi/lo 2x17408 | V hi/lo 2x18432
//               [225280,225536) inv[64]
// ===========================================================================
#define AQ   133120
#define AC   151552
#define AIVF 56320                   // float index of inv[]
#define ATTN2_SMEM 225536

__global__ void __launch_bounds__(256) attn_kernel(float* __restrict__ attn_out)
{
    extern __shared__ char smb[];
    float* smf = (float*)smb;
    const uint32_t sb = smem_u32(smb);
    const int tid = threadIdx.x;
    const int wid = tid >> 5, lane = tid & 31;
    const int hb = blockIdx.y;
    const int q0 = blockIdx.x * 64;
    const int bb = hb & 15, hh = hb >> 4;

    const __nv_bfloat16* kh = g_kBh + (size_t)hb * 512 * 64;
    const __nv_bfloat16* kl = g_kBl + (size_t)hb * 512 * 64;
    const __nv_bfloat16* vh = g_vBh + (size_t)hb * 512 * 64;
    const __nv_bfloat16* vl = g_vBl + (size_t)hb * 512 * 64;

    auto loadK = [&](int nt) {
        const uint32_t base = sb + AC + (uint32_t)(nt & 1) * 36864;
#pragma unroll
        for (int i = 0; i < 8; i++) {
            int f = tid + i * 256;
            int mat = f >> 10, idx = f & 1023;
            int rw = idx >> 3, sg = idx & 7;
            const __nv_bfloat16* g = mat ? kl : kh;
            cpa16(base + mat * 18432 + rw * 144 + sg * 16,
                  g + (size_t)(nt * 128 + rw) * 64 + sg * 8);
        }
    };
    auto loadV = [&](int nt) {
        const uint32_t base = sb + AC + 34816;
#pragma unroll
        for (int i = 0; i < 8; i++) {
            int f = tid + i * 256;
            int mat = f >> 10, idx = f & 1023;
            int rw = idx >> 3, sg = idx & 7;
            const __nv_bfloat16* g = mat ? vl : vh;
            cpa16(base + mat * 18432 + rw * 144 + sg * 16,
                  g + (size_t)(nt * 128 + rw) * 64 + sg * 8);
        }
    };

    // Q tile + K0 (group 0), K1 (group 1)
    {
        const __nv_bfloat16* qhp = g_qBh + ((size_t)hb * 512 + q0) * 64;
        const __nv_bfloat16* qlp = g_qBl + ((size_t)hb * 512 + q0) * 64;
#pragma unroll
        for (int i = 0; i < 4; i++) {
            int f = tid + i * 256;
            int mat = f >> 9, idx = f & 511;
            int rw = idx >> 3, sg = idx & 7;
            const __nv_bfloat16* g = mat ? qlp : qhp;
            cpa16(sb + AQ + mat * 9216 + rw * 144 + sg * 16,
                  g + (size_t)rw * 64 + sg * 8);
        }
        loadK(0); cpa_commit();
        loadK(1); cpa_commit();
    }

    // ---- Phase 1: S = QK^T / 8 via mma ----
    {
        const int qb = wid & 3, nhf = wid >> 2;
        const uint32_t aAddr = sb + AQ +
            (uint32_t)((qb * 16 + (lane & 15)) * 144 + ((lane >> 4) * 8) * 2);
        cpa_wait<1>(); __syncthreads();
        uint32_t aH[4][4], aL[4][4];
#pragma unroll
        for (int ks = 0; ks < 4; ks++) {
            ldm4(aH[ks], aAddr + ks * 32);
            ldm4(aL[ks], aAddr + 9216 + ks * 32);
        }
        const uint32_t bOff = (uint32_t)(
            (nhf * 64 + ((lane >> 4) * 8) + (lane & 7)) * 144 +
            (((lane >> 3) & 1) * 8) * 2);

        for (int nt = 0; nt < 4; nt++) {
            if (nt == 3) { cpa_wait<0>(); __syncthreads(); }
            else if (nt > 0) { cpa_wait<1>(); __syncthreads(); }
            const uint32_t Bb = sb + AC + (uint32_t)(nt & 1) * 36864 + bOff;
            float acc[8][4];
#pragma unroll
            for (int nb = 0; nb < 8; nb++)
#pragma unroll
                for (int j = 0; j < 4; j++) acc[nb][j] = 0.f;
#pragma unroll
            for (int ks = 0; ks < 4; ks++) {
                uint32_t bH[8][2], bL[8][2];
#pragma unroll
                for (int nb4 = 0; nb4 < 4; nb4++) {
                    uint32_t r[4];
                    ldm4(r, Bb + nb4 * 16 * 144 + ks * 32);
                    bH[2 * nb4][0] = r[0]; bH[2 * nb4][1] = r[1];
                    bH[2 * nb4 + 1][0] = r[2]; bH[2 * nb4 + 1][1] = r[3];
                    ldm4(r, Bb + 18432 + nb4 * 16 * 144 + ks * 32);
                    bL[2 * nb4][0] = r[0]; bL[2 * nb4][1] = r[1];
                    bL[2 * nb4 + 1][0] = r[2]; bL[2 * nb4 + 1][1] = r[3];
                }
#pragma unroll
                for (int nb = 0; nb < 8; nb++) mma16816(acc[nb], aH[ks], bH[nb]);
#pragma unroll
                for (int nb = 0; nb < 8; nb++) mma16816(acc[nb], aH[ks], bL[nb]);
#pragma unroll
                for (int nb = 0; nb < 8; nb++) mma16816(acc[nb], aL[ks], bH[nb]);
            }
            int row = qb * 16 + (lane >> 2);
#pragma unroll
            for (int nb = 0; nb < 8; nb++) {
                int col = nt * 128 + nhf * 64 + nb * 8 + (lane & 3) * 2;
                *(float2*)&smf[row * 520 + col] =
                    make_float2(acc[nb][0] * 0.125f, acc[nb][1] * 0.125f);
                *(float2*)&smf[(row + 8) * 520 + col] =
                    make_float2(acc[nb][2] * 0.125f, acc[nb][3] * 0.125f);
            }
            __syncthreads();
            if (nt < 2) { loadK(nt + 2); cpa_commit(); }
        }
    }

    // prefetch V0 (K buffers fully drained), overlapped with softmax
    loadV(0); cpa_commit();

    // ---- Phase 2: softmax + attn writeback (8 warps x 8 rows) ----
    {
        for (int qi = 0; qi < 8; qi++) {
            int ql = wid * 8 + qi;
            float* srow = &smf[ql * 520];
            float m = -3.4e38f;
#pragma unroll
            for (int s = 0; s < 4; s++) {
                float4 v = *(const float4*)&srow[(s * 32 + lane) * 4];
                m = fmaxf(m, fmaxf(fmaxf(v.x, v.y), fmaxf(v.z, v.w)));
            }
#pragma unroll
            for (int off = 16; off >= 1; off >>= 1)
                m = fmaxf(m, __shfl_xor_sync(0xffffffffu, m, off));
            float sum = 0.f;
#pragma unroll
            for (int s = 0; s < 4; s++) {
                float4* p = (float4*)&srow[(s * 32 + lane) * 4];
                float4 v = *p;
                v.x = __expf(v.x - m); v.y = __expf(v.y - m);
                v.z = __expf(v.z - m); v.w = __expf(v.w - m);
                *p = v;
                sum += v.x + v.y + v.z + v.w;
            }
#pragma unroll
            for (int off = 16; off >= 1; off >>= 1)
                sum += __shfl_xor_sync(0xffffffffu, sum, off);
            float iv = 1.0f / sum;
            if (lane == 0) smf[AIVF + ql] = iv;
            float* drow = attn_out + ((size_t)hb * 512 + q0 + ql) * 512;
#pragma unroll
            for (int s = 0; s < 4; s++) {
                float4 v = *(const float4*)&srow[(s * 32 + lane) * 4];
                v.x *= iv; v.y *= iv; v.z *= iv; v.w *= iv;
                *(float4*)&drow[(s * 32 + lane) * 4] = v;
            }
        }
    }
    __syncthreads();

    // ---- Phase 3: O = P V via mma (P converted per tile to bf16 hi/lo) ----
    {
        const int qb = wid & 3, dvh = wid >> 2;
        float oacc[4][4];
#pragma unroll
        for (int db = 0; db < 4; db++)
#pragma unroll
            for (int j = 0; j < 4; j++) oacc[db][j] = 0.f;

        const uint32_t pAddr = sb + AC +
            (uint32_t)((qb * 16 + (lane & 15)) * 272 + (lane >> 4) * 16);
        const uint32_t vAddr = sb + AC + 34816 +
            (uint32_t)((lane & 15) * 144 + ((lane >> 4) * 8 + dvh * 32) * 2);

        for (int nt = 0; nt < 4; nt++) {
            // convert P tile (overlaps in-flight V cp.async)
#pragma unroll
            for (int it = 0; it < 8; it++) {
                int idx = tid + it * 256;
                int qq = idx >> 5, c4 = idx & 31;
                float4 s = *(const float4*)&smf[qq * 520 + nt * 128 + c4 * 4];
                float iv = smf[AIVF + qq];
                float p[4] = { s.x * iv, s.y * iv, s.z * iv, s.w * iv };
                __nv_bfloat16 h[4], l[4];
#pragma unroll
                for (int j = 0; j < 4; j++) {
                    h[j] = __float2bfloat16(p[j]);
                    l[j] = __float2bfloat16(p[j] - __bfloat162float(h[j]));
                }
                __nv_bfloat162 hp0 = __halves2bfloat162(h[0], h[1]);
                __nv_bfloat162 hp1 = __halves2bfloat162(h[2], h[3]);
                __nv_bfloat162 lp0 = __halves2bfloat162(l[0], l[1]);
                __nv_bfloat162 lp1 = __halves2bfloat162(l[2], l[3]);
                uint2 uh, ul;
                uh.x = *(uint32_t*)&hp0; uh.y = *(uint32_t*)&hp1;
                ul.x = *(uint32_t*)&lp0; ul.y = *(uint32_t*)&lp1;
                *(uint2*)(smb + AC + qq * 272 + c4 * 8) = uh;
                *(uint2*)(smb + AC + 17408 + qq * 272 + c4 * 8) = ul;
            }
            cpa_wait<0>(); __syncthreads();
#pragma unroll
            for (int ks = 0; ks < 8; ks++) {
                uint32_t pH[4], pL[4];
                ldm4(pH, pAddr + ks * 32);
                ldm4(pL, pAddr + 17408 + ks * 32);
                uint32_t vH[4][2], vL[4][2], r[4];
                ldm4t(r, vAddr + ks * 16 * 144);
                vH[0][0] = r[0]; vH[0][1] = r[1]; vH[1][0] = r[2]; vH[1][1] = r[3];
                ldm4t(r, vAddr + ks * 16 * 144 + 32);
                vH[2][0] = r[0]; vH[2][1] = r[1]; vH[3][0] = r[2]; vH[3][1] = r[3];
                ldm4t(r, vAddr + 18432 + ks * 16 * 144);
                vL[0][0] = r[0]; vL[0][1] = r[1]; vL[1][0] = r[2]; vL[1][1] = r[3];
                ldm4t(r, vAddr + 18432 + ks * 16 * 144 + 32);
                vL[2][0] = r[0]; vL[2][1] = r[1]; vL[3][0] = r[2]; vL[3][1] = r[3];
#pragma unroll
                for (int db = 0; db < 4; db++) mma16816(oacc[db], pH, vH[db]);
#pragma unroll
                for (int db = 0; db < 4; db++) mma16816(oacc[db], pH, vL[db]);
#pragma unroll
                for (int db = 0; db < 4; db++) mma16816(oacc[db], pL, vH[db]);
            }
            __syncthreads();
            if (nt < 3) { loadV(nt + 1); cpa_commit(); }
        }

        int row = qb * 16 + (lane >> 2);
#pragma unroll
        for (int db = 0; db < 4; db++) {
            int dv = dvh * 32 + db * 8 + (lane & 3) * 2;
            *(float2*)&g_act[(((size_t)bb * 512 + q0 + row) * 8 + hh) * 64 + dv] =
                make_float2(oacc[db][0], oacc[db][1]);
            *(float2*)&g_act[(((size_t)bb * 512 + q0 + row + 8) * 8 + hh) * 64 + dv] =
                make_float2(oacc[db][2], oacc[db][3]);
        }
    }
}

// ===========================================================================
// FC: out[b][o] = sum_i act[b][i]*Wf[o][i], I=262144. 256-way split-K.
// XOR-swizzled act staging (conflict-free); weight index = logical k (R6 fix).
// ===========================================================================
#define FC_KC 1024
#define FC_SMEM_BYTES (8 * FC_KC * 8)

__global__ void __launch_bounds__(256, 2) fc_kernel(const float* __restrict__ Wf)
{
    extern __shared__ float2 sm2[];
    const int tid = threadIdx.x;
    const int k0 = blockIdx.x * FC_KC;
    const int o0 = blockIdx.y * 32;

    const float4* act4 = (const float4*)g_act;
    float* smf = (float*)sm2;
    for (int f = tid; f < 4096; f += 256) {
        int b = f >> 8, c = f & 255;
        float4 v = act4[(size_t)b * 65536 + (k0 >> 2) + c];
        int b2 = b >> 1, lo = b & 1;
        int cx = (c >> 2) & 3;
        int base = b2 * FC_KC + c * 4;
        smf[2 * (base + (0 ^ cx)) + lo] = v.x;
        smf[2 * (base + (1 ^ cx)) + lo] = v.y;
        smf[2 * (base + (2 ^ cx)) + lo] = v.z;
        smf[2 * (base + (3 ^ cx)) + lo] = v.w;
    }
    __syncthreads();

    const int warp = tid >> 5, lane = tid & 31;
    const int ob = o0 + warp * 4;
    const int xv = (lane >> 2) & 3;

    u64t acc[4][8];
#pragma unroll
    for (int j = 0; j < 4; j++)
#pragma unroll
        for (int b2 = 0; b2 < 8; b2++) acc[j][b2] = 0ull;

    const float* wr[4] = {
        Wf + (size_t)(ob + 0) * 262144 + k0, Wf + (size_t)(ob + 1) * 262144 + k0,
        Wf + (size_t)(ob + 2) * 262144 + k0, Wf + (size_t)(ob + 3) * 262144 + k0 };

    for (int i0 = lane * 4; i0 < FC_KC; i0 += 128) {
        float wv[4][4];
#pragma unroll
        for (int j = 0; j < 4; j++) {
            float4 w4 = *(const float4*)(wr[j] + i0);
            wv[j][0] = w4.x; wv[j][1] = w4.y; wv[j][2] = w4.z; wv[j][3] = w4.w;
        }
#pragma unroll
        for (int kk = 0; kk < 4; kk++) {
            const int ik = i0 + (kk ^ xv);
            u64t a[8];
#pragma unroll
            for (int b2 = 0; b2 < 8; b2++)
                a[b2] = *(const u64t*)&sm2[b2 * FC_KC + ik];
#pragma unroll
            for (int j = 0; j < 4; j++) {
                u64t wd = dup2(wv[j][kk]);
#pragma unroll
                for (int b2 = 0; b2 < 8; b2++)
                    fma2(acc[j][b2], wd, a[b2]);
            }
        }
    }

#pragma unroll
    for (int j = 0; j < 4; j++)
#pragma unroll
        for (int b2 = 0; b2 < 8; b2++) {
#pragma unroll
            for (int off = 16; off >= 1; off >>= 1) {
                u64t o = __shfl_down_sync(0xffffffffu, acc[j][b2], off);
                acc[j][b2] = add2(acc[j][b2], o);
            }
        }
    if (lane == 0) {
#pragma unroll
        for (int j = 0; j < 4; j++) {
            size_t base = ((size_t)blockIdx.x * 512 + ob + j) * 16;
#pragma unroll
            for (int b2 = 0; b2 < 8; b2++) {
                float2 f = unp2(acc[j][b2]);
                g_part[base + 2 * b2]     = f.x;
                g_part[base + 2 * b2 + 1] = f.y;
            }
        }
    }
}

__global__ void __launch_bounds__(256) reduce_fc(const float* __restrict__ bf,
                                                 float* __restrict__ out)
{
    __shared__ float red[8][33];
    const int t = threadIdx.x;
    const int oi = blockIdx.x * 32 + (t & 31);
    const int part = t >> 5;
    const int o = oi >> 4, b = oi & 15;
    float s = 0.f;
#pragma unroll 8
    for (int ks = part * 32; ks < part * 32 + 32; ks++)
        s += g_part[((size_t)ks * 512 + o) * 16 + b];
    red[part][t & 31] = s;
    __syncthreads();
    if (t < 32) {
        float tot = 0.f;
#pragma unroll
        for (int j = 0; j < 8; j++) tot += red[j][t];
        int oo = blockIdx.x * 32 + t;
        out[(oo & 15) * 512 + (oo >> 4)] = tot + bf[oo >> 4];
    }
}

// ===========================================================================
extern "C" void kernel_launch(void* const* d_in, const int* in_sizes, int n_in,
                              void* d_out, int out_size)
{
    const float* q  = (const float*)d_in[0];
    const float* k  = (const float*)d_in[1];
    const float* v  = (const float*)d_in[2];
    const float* Wq = (const float*)d_in[3];
    const float* bq = (const float*)d_in[4];
    const float* Wk = (const float*)d_in[5];
    const float* bk = (const float*)d_in[6];
    const float* Wv = (const float*)d_in[7];
    const float* bv = (const float*)d_in[8];
    const float* Wf = (const float*)d_in[9];
    const float* bf = (const float*)d_in[10];
    float* out = (float*)d_out;

    cudaFuncSetAttribute(proj_mma, cudaFuncAttributeMaxDynamicSharedMemorySize, PJ_SMEM);
    cudaFuncSetAttribute(attn_kernel, cudaFuncAttributeMaxDynamicSharedMemorySize,
                         ATTN2_SMEM);
    cudaFuncSetAttribute(fc_kernel, cudaFuncAttributeMaxDynamicSharedMemorySize,
                         FC_SMEM_BYTES);

    cvt_kernel<<<13056, 256>>>(q, k, v, Wq, Wk, Wv);
    proj_mma<<<dim3(4, 64, 3), 256, PJ_SMEM>>>(bq, bk, bv);
    attn_kernel<<<dim3(8, 128), 256, ATTN2_SMEM>>>(out + 8192);
    fc_kernel<<<dim3(256, 16), 256, FC_SMEM_BYTES>>>(Wf);
    reduce_fc<<<256, 256>>>(bf, out);
}